// round 5
// baseline (speedup 1.0000x reference)
#include <cuda_runtime.h>
#include <cuda_bf16.h>
#include <cstdint>
#include <cstddef>

// Problem constants
#define BB 8
#define SEQ 4096
#define CC 1024
#define HH 16
#define DD 64
#define MM (BB*SEQ)          // 32768
#define C3 (3*CC)            // 3072
#define BH (BB*HH)           // 128
#define EPS 1e-6f
#define K2 2048              // split operand width (hi | lo)

// ---------------- scratch (device globals; no allocation allowed) ----------------
__device__ float g_qkv[(size_t)MM * C3];          // q | k | v  (f32, focus in-place)
__device__ float g_kv[(size_t)BH * DD * DD];
__device__ float g_ksum[BH * DD];
__device__ __nv_bfloat16 g_x2[(size_t)MM * K2];   // x split   [M][hi(1024)|lo(1024)]
__device__ __nv_bfloat16 g_o2[(size_t)MM * K2];   // o split
__device__ __nv_bfloat16 g_wq2[(size_t)C3 * K2];  // qkv_w split
__device__ __nv_bfloat16 g_wp2[(size_t)CC * K2];  // proj_w split

// ================================ helpers ========================================
__device__ __forceinline__ uint32_t smem_u32(const void* p) {
    uint32_t a;
    asm("{ .reg .u64 t; cvta.to.shared.u64 t, %1; cvt.u32.u64 %0, t; }" : "=r"(a) : "l"(p));
    return a;
}
__device__ __forceinline__ void cpa16(uint32_t sa, const void* g) {
    size_t ga = __cvta_generic_to_global(g);
    asm volatile("cp.async.cg.shared.global [%0], [%1], 16;" :: "r"(sa), "l"(ga) : "memory");
}
__device__ __forceinline__ void ldsm4(uint32_t* d, uint32_t addr) {
    asm volatile("ldmatrix.sync.aligned.m8n8.x4.shared.b16 {%0,%1,%2,%3}, [%4];"
        : "=r"(d[0]), "=r"(d[1]), "=r"(d[2]), "=r"(d[3]) : "r"(addr));
}
__device__ __forceinline__ void mma_bf16(float* c, const uint32_t* a, const uint32_t* b) {
    asm volatile("mma.sync.aligned.m16n8k16.row.col.f32.bf16.bf16.f32 "
        "{%0,%1,%2,%3}, {%4,%5,%6,%7}, {%8,%9}, {%0,%1,%2,%3};"
        : "+f"(c[0]), "+f"(c[1]), "+f"(c[2]), "+f"(c[3])
        : "r"(a[0]), "r"(a[1]), "r"(a[2]), "r"(a[3]), "r"(b[0]), "r"(b[1]));
}
#define SW128(o) ((o) ^ (((o) >> 3) & 0x70))

// ============================ HMMA split GEMM ====================================
// C[m,n] = sum_k A[m,k]*B[n,k] (fp32 via bf16 split: Ah*Bh + Al*Bh + Ah*Bl)
// BM=128, BN=128, BK=64; 512 threads; warp tile 32x32 (4x4 grid); 3-stage cp.async.
#define GBM 128
#define GBN 128
#define GBK 64
#define NCH (CC / GBK)          // 16 k-chunks
#define MATB (128 * 128)        // 16384 B per matrix tile (128 rows x 128B, SW128)
#define STG (4 * MATB)          // Ah|Al|Bh|Bl = 65536 B per stage
#define NSTG 3
#define GSMEM (NSTG * STG)      // 196608 B

__device__ __forceinline__ void g2s_chunk(uint32_t sbase,
    const __nv_bfloat16* __restrict__ A2, const __nv_bfloat16* __restrict__ B2,
    int m0, int n0, int k0, int t)
{
#pragma unroll
    for (int i = 0; i < 2; i++) {
        int idx = t + i * 512;            // 1024 16B-chunks per matrix
        int r = idx >> 3, j = idx & 7;
        uint32_t off = r * 128 + j * 16;
        uint32_t sw = SW128(off);
        const __nv_bfloat16* ga = A2 + (size_t)(m0 + r) * K2 + k0 + j * 8;
        cpa16(sbase + 0 * MATB + sw, ga);
        cpa16(sbase + 1 * MATB + sw, ga + CC);
        const __nv_bfloat16* gb = B2 + (size_t)(n0 + r) * K2 + k0 + j * 8;
        cpa16(sbase + 2 * MATB + sw, gb);
        cpa16(sbase + 3 * MATB + sw, gb + CC);
    }
}

__global__ __launch_bounds__(512) void gemm_mma(
    const __nv_bfloat16* __restrict__ A2, const __nv_bfloat16* __restrict__ B2,
    const float* __restrict__ bias, float* __restrict__ C, int Nn)
{
    extern __shared__ char sm[];
    const uint32_t sb = smem_u32(sm);
    const int t = threadIdx.x, lane = t & 31, w = t >> 5;
    const int wm = (w & 3) * 32, wn = (w >> 2) * 32;
    const int m0 = blockIdx.y * GBM, n0 = blockIdx.x * GBN;

    const int lrow = lane & 15;           // ldmatrix source row within 16
    const int lcol = (lane >> 4) << 3;    // ldmatrix k-col select (0 or 8)

    float acc[2][4][4];
#pragma unroll
    for (int i = 0; i < 2; i++)
#pragma unroll
        for (int j = 0; j < 4; j++)
#pragma unroll
            for (int r = 0; r < 4; r++) acc[i][j][r] = 0.f;

    // prologue: chunks 0,1 into stages 0,1
    g2s_chunk(sb, A2, B2, m0, n0, 0, t);
    asm volatile("cp.async.commit_group;" ::: "memory");
    g2s_chunk(sb + STG, A2, B2, m0, n0, GBK, t);
    asm volatile("cp.async.commit_group;" ::: "memory");

    int stage = 0, wstage = 2;
    for (int c = 0; c < NCH; c++) {
        if (c == NCH - 1) asm volatile("cp.async.wait_group 0;" ::: "memory");
        else              asm volatile("cp.async.wait_group 1;" ::: "memory");
        __syncthreads();
        if (c + 2 < NCH) {
            g2s_chunk(sb + wstage * STG, A2, B2, m0, n0, (c + 2) * GBK, t);
            asm volatile("cp.async.commit_group;" ::: "memory");
            wstage = wstage == 2 ? 0 : wstage + 1;
        }
        const uint32_t st = sb + stage * STG;
        stage = stage == 2 ? 0 : stage + 1;

#pragma unroll
        for (int ks = 0; ks < 4; ks++) {
            const int kb = ks * 16;
            uint32_t ah[2][4], al[2][4];
#pragma unroll
            for (int mi = 0; mi < 2; mi++) {
                uint32_t off = (wm + mi * 16 + lrow) * 128 + (kb + lcol) * 2;
                uint32_t sw = SW128(off);
                ldsm4(ah[mi], st + sw);
                ldsm4(al[mi], st + MATB + sw);
            }
            uint32_t bh[4][2], bl[4][2];
#pragma unroll
            for (int bj = 0; bj < 2; bj++) {
                uint32_t r4[4], s4[4];
                uint32_t off = (wn + bj * 16 + lrow) * 128 + (kb + lcol) * 2;
                uint32_t sw = SW128(off);
                ldsm4(r4, st + 2 * MATB + sw);
                ldsm4(s4, st + 3 * MATB + sw);
                bh[2 * bj + 0][0] = r4[0]; bh[2 * bj + 0][1] = r4[2];
                bh[2 * bj + 1][0] = r4[1]; bh[2 * bj + 1][1] = r4[3];
                bl[2 * bj + 0][0] = s4[0]; bl[2 * bj + 0][1] = s4[2];
                bl[2 * bj + 1][0] = s4[1]; bl[2 * bj + 1][1] = s4[3];
            }
            // 3 product passes; consecutive MMAs hit independent accumulators
#pragma unroll
            for (int mi = 0; mi < 2; mi++)
#pragma unroll
                for (int nj = 0; nj < 4; nj++)
                    mma_bf16(acc[mi][nj], ah[mi], bh[nj]);
#pragma unroll
            for (int mi = 0; mi < 2; mi++)
#pragma unroll
                for (int nj = 0; nj < 4; nj++)
                    mma_bf16(acc[mi][nj], al[mi], bh[nj]);
#pragma unroll
            for (int mi = 0; mi < 2; mi++)
#pragma unroll
                for (int nj = 0; nj < 4; nj++)
                    mma_bf16(acc[mi][nj], ah[mi], bl[nj]);
        }
    }

    // epilogue
    const int group = lane >> 2, tig = lane & 3;
#pragma unroll
    for (int mi = 0; mi < 2; mi++)
#pragma unroll
        for (int nj = 0; nj < 4; nj++) {
            int r0 = m0 + wm + mi * 16 + group;
            int cc0 = n0 + wn + nj * 8 + tig * 2;
            float b0 = 0.f, b1 = 0.f;
            if (bias) { b0 = bias[cc0]; b1 = bias[cc0 + 1]; }
            float2 v0 = make_float2(acc[mi][nj][0] + b0, acc[mi][nj][1] + b1);
            float2 v1 = make_float2(acc[mi][nj][2] + b0, acc[mi][nj][3] + b1);
            *(float2*)(C + (size_t)r0 * Nn + cc0)       = v0;
            *(float2*)(C + (size_t)(r0 + 8) * Nn + cc0) = v1;
        }
}

// ============================ split f32 -> (hi|lo) bf16 ==========================
__global__ __launch_bounds__(256) void split_kernel(
    const float* __restrict__ in, __nv_bfloat16* __restrict__ out, int rows)
{
    size_t idx = (size_t)blockIdx.x * 256 + threadIdx.x;
    size_t row = idx >> 8;
    if (row >= (size_t)rows) return;
    int c4 = (int)(idx & 255) << 2;
    float4 v = *(const float4*)(in + row * CC + c4);
    float vv[4] = {v.x, v.y, v.z, v.w};
    __nv_bfloat16 hb[4], lb[4];
#pragma unroll
    for (int j = 0; j < 4; j++) {
        hb[j] = __float2bfloat16(vv[j]);
        lb[j] = __float2bfloat16(vv[j] - __bfloat162float(hb[j]));
    }
    *(uint64_t*)(out + row * K2 + c4)      = *(uint64_t*)hb;
    *(uint64_t*)(out + row * K2 + CC + c4) = *(uint64_t*)lb;
}

// ================================== focus ========================================
__global__ __launch_bounds__(256) void focus_kernel(
    const float* __restrict__ scale, const float* __restrict__ pos_enc)
{
    const int row = blockIdx.x;
    const int n = row & (SEQ - 1);
    float* qp = g_qkv + (size_t)row * C3;
    float* kp = qp + CC;
    const int t = threadIdx.x;
    const int c0 = t * 4;

    float4 q4 = *(float4*)(qp + c0);
    float4 k4 = *(float4*)(kp + c0);
    const float4 pe  = *(const float4*)(pos_enc + (size_t)n * CC + c0);
    const float4 sc4 = *(const float4*)(scale + c0);

    float qv[4] = {q4.x, q4.y, q4.z, q4.w};
    float kv[4] = {k4.x + pe.x, k4.y + pe.y, k4.z + pe.z, k4.w + pe.w};
    float sv[4] = {sc4.x, sc4.y, sc4.z, sc4.w};

    float s2q = 0.f, s6q = 0.f, s2k = 0.f, s6k = 0.f;
#pragma unroll
    for (int j = 0; j < 4; j++) {
        float sc = log1pf(expf(sv[j]));
        float q = (fmaxf(qv[j], 0.f) + EPS) / sc;
        float k = (fmaxf(kv[j], 0.f) + EPS) / sc;
        qv[j] = q; kv[j] = k;
        float q2 = q * q, k2 = k * k;
        s2q += q2; s2k += k2;
        float q3 = q2 * q, k3 = k2 * k;
        s6q += q3 * q3; s6k += k3 * k3;
    }
    __shared__ float red[8][4];
    const int lid = t & 31, wid = t >> 5;
#pragma unroll
    for (int o = 16; o > 0; o >>= 1) {
        s2q += __shfl_xor_sync(0xffffffffu, s2q, o);
        s6q += __shfl_xor_sync(0xffffffffu, s6q, o);
        s2k += __shfl_xor_sync(0xffffffffu, s2k, o);
        s6k += __shfl_xor_sync(0xffffffffu, s6k, o);
    }
    if (lid == 0) { red[wid][0] = s2q; red[wid][1] = s6q; red[wid][2] = s2k; red[wid][3] = s6k; }
    __syncthreads();
    float t2q = 0.f, t6q = 0.f, t2k = 0.f, t6k = 0.f;
#pragma unroll
    for (int wq = 0; wq < 8; wq++) {
        t2q += red[wq][0]; t6q += red[wq][1]; t2k += red[wq][2]; t6k += red[wq][3];
    }
    const float fq = sqrtf(t2q / t6q);
    const float fk = sqrtf(t2k / t6k);

    float4 qo, ko;
    float* qvo = (float*)&qo; float* kvo = (float*)&ko;
#pragma unroll
    for (int j = 0; j < 4; j++) {
        qvo[j] = qv[j] * qv[j] * qv[j] * fq;
        kvo[j] = kv[j] * kv[j] * kv[j] * fk;
    }
    *(float4*)(qp + c0) = qo;
    *(float4*)(kp + c0) = ko;
}

__global__ void zero_kv_kernel()
{
    int i = blockIdx.x * 256 + threadIdx.x;
    if (i < BH * DD * DD) g_kv[i] = 0.f;
    if (i < BH * DD)      g_ksum[i] = 0.f;
}

// ==================================== kv =========================================
#define NSPLIT 8
#define NCHUNK (SEQ / NSPLIT)
__global__ __launch_bounds__(64) void kv_kernel()
{
    const int bh = blockIdx.x;
    const int sp = blockIdx.y;
    const int b = bh >> 4, h = bh & 15;
    const int n0 = sp * NCHUNK;
    __shared__ float ks[32][64];
    __shared__ float vs[32][64];
    const int t = threadIdx.x;
    const int tc = (t >> 3) << 3;
    const int td = (t & 7) << 3;
    unsigned long long acc2[8][4];
#pragma unroll
    for (int i = 0; i < 8; i++)
#pragma unroll
        for (int j = 0; j < 4; j++) acc2[i][j] = 0ULL;
    float ksacc = 0.f;

    for (int nt = 0; nt < NCHUNK; nt += 32) {
#pragma unroll
        for (int l = 0; l < 8; l++) {
            int idx4 = t + l * 64;
            int nn = idx4 >> 4, q4 = (idx4 & 15) << 2;
            size_t base = ((size_t)(b * SEQ + n0 + nt + nn)) * C3 + h * DD + q4;
            *(float4*)&ks[nn][q4] = *(const float4*)&g_qkv[base + CC];
            *(float4*)&vs[nn][q4] = *(const float4*)&g_qkv[base + 2 * CC];
        }
        __syncthreads();
#pragma unroll 4
        for (int nn = 0; nn < 32; nn++) {
            float a[8];
            *(float4*)(a)      = *(float4*)&ks[nn][tc];
            *(float4*)(a + 4)  = *(float4*)&ks[nn][tc + 4];
            unsigned long long b2[4];
            *(ulonglong2*)(b2)     = *(const ulonglong2*)(&vs[nn][td]);
            *(ulonglong2*)(b2 + 2) = *(const ulonglong2*)(&vs[nn][td + 4]);
#pragma unroll
            for (int i = 0; i < 8; i++) {
                unsigned long long a2;
                asm("mov.b64 %0, {%1, %1};" : "=l"(a2) : "f"(a[i]));
#pragma unroll
                for (int j = 0; j < 4; j++)
                    asm("fma.rn.f32x2 %0, %1, %2, %0;" : "+l"(acc2[i][j]) : "l"(a2), "l"(b2[j]));
            }
            ksacc += ks[nn][t];
        }
        __syncthreads();
    }
#pragma unroll
    for (int i = 0; i < 8; i++)
#pragma unroll
        for (int j = 0; j < 4; j++) {
            float lo, hi;
            asm("mov.b64 {%0, %1}, %2;" : "=f"(lo), "=f"(hi) : "l"(acc2[i][j]));
            atomicAdd(&g_kv[((size_t)bh * DD + tc + i) * DD + td + 2 * j], lo);
            atomicAdd(&g_kv[((size_t)bh * DD + tc + i) * DD + td + 2 * j + 1], hi);
        }
    atomicAdd(&g_ksum[bh * DD + t], ksacc);
}

// ============ o kernel: writes split bf16 (hi|lo) directly into g_o2 =============
__global__ __launch_bounds__(256) void o_kernel()
{
    const int bh = blockIdx.x;
    const int ic = blockIdx.y;
    const int b = bh >> 4, h = bh & 15;
    const int i0 = ic * 64;
    __shared__ float qs[64][68];
    __shared__ float kvs[64][64];
    __shared__ float ks_s[64];
    __shared__ float z_s[64];
    const int t = threadIdx.x;

    for (int idx = t; idx < DD * DD; idx += 256)
        kvs[idx >> 6][idx & 63] = g_kv[(size_t)bh * DD * DD + idx];
    if (t < 64) ks_s[t] = g_ksum[bh * DD + t];
    for (int idx = t; idx < 64 * 64; idx += 256) {
        int r = idx >> 6, c = idx & 63;
        qs[c][r] = g_qkv[((size_t)(b * SEQ + i0 + r)) * C3 + h * DD + c];
    }
    __syncthreads();

    if (t < 64) {
        float s = 0.f;
#pragma unroll 8
        for (int c = 0; c < 64; c++) s += qs[c][t] * ks_s[c];
        z_s[t] = 1.0f / (s + EPS);
    }
    __syncthreads();

    const int tm = (t >> 5) << 3;
    const int tn = (t & 31) << 1;
    float acc[8][2] = {};
#pragma unroll 8
    for (int c = 0; c < 64; c++) {
        float a[8];
        *(float4*)(a)     = *(float4*)&qs[c][tm];
        *(float4*)(a + 4) = *(float4*)&qs[c][tm + 4];
        float2 bv = *(float2*)&kvs[c][tn];
#pragma unroll
        for (int i = 0; i < 8; i++) {
            acc[i][0] += a[i] * bv.x;
            acc[i][1] += a[i] * bv.y;
        }
    }
#pragma unroll
    for (int i = 0; i < 8; i++) {
        float z = z_s[tm + i];
        float v0 = acc[i][0] * z, v1 = acc[i][1] * z;
        __nv_bfloat16 hb0 = __float2bfloat16(v0), hb1 = __float2bfloat16(v1);
        __nv_bfloat16 lb0 = __float2bfloat16(v0 - __bfloat162float(hb0));
        __nv_bfloat16 lb1 = __float2bfloat16(v1 - __bfloat162float(hb1));
        size_t off = ((size_t)(b * SEQ + i0 + tm + i)) * K2 + h * DD + tn;
        __nv_bfloat162 hp; hp.x = hb0; hp.y = hb1;
        __nv_bfloat162 lp; lp.x = lb0; lp.y = lb1;
        *(__nv_bfloat162*)(g_o2 + off)      = hp;
        *(__nv_bfloat162*)(g_o2 + off + CC) = lp;
    }
}

// =================================================================================
extern "C" void kernel_launch(void* const* d_in, const int* in_sizes, int n_in,
                              void* d_out, int out_size)
{
    const float* x       = (const float*)d_in[0];
    const float* scale   = (const float*)d_in[1];
    const float* pos_enc = (const float*)d_in[2];
    const float* qkv_w   = (const float*)d_in[3];
    const float* proj_w  = (const float*)d_in[4];
    const float* proj_b  = (const float*)d_in[5];
    float* out = (float*)d_out;

    float *qkv_p = nullptr;
    __nv_bfloat16 *x2_p = nullptr, *o2_p = nullptr, *wq2_p = nullptr, *wp2_p = nullptr;
    cudaGetSymbolAddress((void**)&qkv_p, g_qkv);
    cudaGetSymbolAddress((void**)&x2_p, g_x2);
    cudaGetSymbolAddress((void**)&o2_p, g_o2);
    cudaGetSymbolAddress((void**)&wq2_p, g_wq2);
    cudaGetSymbolAddress((void**)&wp2_p, g_wp2);

    cudaFuncSetAttribute(gemm_mma, cudaFuncAttributeMaxDynamicSharedMemorySize, GSMEM);

    // 0) bf16 splits of x and weights
    split_kernel<<<MM, 256>>>(x, x2_p, MM);
    split_kernel<<<C3, 256>>>(qkv_w, wq2_p, C3);
    split_kernel<<<CC, 256>>>(proj_w, wp2_p, CC);
    // 1) qkv = x @ qkv_w^T  (HMMA, bf16-split, fp32 accumulate)
    gemm_mma<<<dim3(C3 / GBN, MM / GBM), 512, GSMEM>>>(x2_p, wq2_p, nullptr, qkv_p, C3);
    // 2) focusing / activation (in-place on q,k)
    focus_kernel<<<MM, 256>>>(scale, pos_enc);
    // 3) kv = k^T v (+ ksum)
    zero_kv_kernel<<<(BH * DD * DD + 255) / 256, 256>>>();
    kv_kernel<<<dim3(BH, NSPLIT), 64>>>();
    // 4) o = z * (q @ kv), written as split bf16 in merged-head layout
    o_kernel<<<dim3(BH, SEQ / 64), 256>>>();
    // 5) out = o @ proj_w^T + proj_b  (HMMA)
    gemm_mma<<<dim3(CC / GBN, MM / GBM), 512, GSMEM>>>(o2_p, wp2_p, proj_b, out, CC);
}

// round 6
// speedup vs baseline: 1.5432x; 1.5432x over previous
#include <cuda_runtime.h>
#include <cuda_bf16.h>
#include <cstdint>
#include <cstddef>

// Problem constants
#define BB 8
#define SEQ 4096
#define CC 1024
#define HH 16
#define DD 64
#define MM (BB*SEQ)          // 32768
#define C3 (3*CC)            // 3072
#define BH (BB*HH)           // 128
#define EPS 1e-6f
#define K2 2048              // split operand width (hi | lo)

// ---------------- scratch (device globals; no allocation allowed) ----------------
__device__ float g_qkv[(size_t)MM * C3];          // q | k | v  (f32, focus in-place)
__device__ float g_kv[(size_t)BH * DD * DD];
__device__ float g_ksum[BH * DD];
__device__ __nv_bfloat16 g_x2[(size_t)MM * K2];   // x split   [M][hi(1024)|lo(1024)]
__device__ __nv_bfloat16 g_o2[(size_t)MM * K2];   // o split
__device__ __nv_bfloat16 g_wq2[(size_t)C3 * K2];  // qkv_w split
__device__ __nv_bfloat16 g_wp2[(size_t)CC * K2];  // proj_w split

// ================================ helpers ========================================
__device__ __forceinline__ uint32_t smem_u32(const void* p) {
    uint32_t a;
    asm("{ .reg .u64 t; cvta.to.shared.u64 t, %1; cvt.u32.u64 %0, t; }" : "=r"(a) : "l"(p));
    return a;
}
__device__ __forceinline__ void cpa16(uint32_t sa, const void* g) {
    size_t ga = __cvta_generic_to_global(g);
    asm volatile("cp.async.cg.shared.global [%0], [%1], 16;" :: "r"(sa), "l"(ga) : "memory");
}
__device__ __forceinline__ void ldsm4(uint32_t* d, uint32_t addr) {
    asm volatile("ldmatrix.sync.aligned.m8n8.x4.shared.b16 {%0,%1,%2,%3}, [%4];"
        : "=r"(d[0]), "=r"(d[1]), "=r"(d[2]), "=r"(d[3]) : "r"(addr));
}
__device__ __forceinline__ void mma_bf16(float* c, const uint32_t* a, const uint32_t* b) {
    asm volatile("mma.sync.aligned.m16n8k16.row.col.f32.bf16.bf16.f32 "
        "{%0,%1,%2,%3}, {%4,%5,%6,%7}, {%8,%9}, {%0,%1,%2,%3};"
        : "+f"(c[0]), "+f"(c[1]), "+f"(c[2]), "+f"(c[3])
        : "r"(a[0]), "r"(a[1]), "r"(a[2]), "r"(a[3]), "r"(b[0]), "r"(b[1]));
}
#define SW128(o) ((o) ^ (((o) >> 3) & 0x70))

// ============================ HMMA split GEMM ====================================
// C[m,n] = sum_k A[m,k]*B[n,k] (fp32 via bf16 split: Ah*Bh + Al*Bh + Ah*Bl)
// BM=128, BN=128, BK=64; 256 threads; warp tile 64x32 (2x4); 3-stage cp.async;
// fragment double-buffering across k-substeps; deferred g2s prefetch.
#define GBM 128
#define GBN 128
#define GBK 64
#define NCH (CC / GBK)          // 16 k-chunks
#define MATB (128 * 128)        // 16384 B per matrix tile (128 rows x 128B, SW128)
#define STG (4 * MATB)          // Ah|Al|Bh|Bl = 65536 B per stage
#define NSTG 3
#define GSMEM (NSTG * STG)      // 196608 B

__device__ __forceinline__ void g2s_chunk(uint32_t sbase,
    const __nv_bfloat16* __restrict__ A2, const __nv_bfloat16* __restrict__ B2,
    int m0, int n0, int k0, int t)
{
#pragma unroll
    for (int i = 0; i < 4; i++) {
        int idx = t + i * 256;            // 1024 16B-chunks per matrix
        int r = idx >> 3, j = idx & 7;
        uint32_t off = r * 128 + j * 16;
        uint32_t sw = SW128(off);
        const __nv_bfloat16* ga = A2 + (size_t)(m0 + r) * K2 + k0 + j * 8;
        cpa16(sbase + 0 * MATB + sw, ga);
        cpa16(sbase + 1 * MATB + sw, ga + CC);
        const __nv_bfloat16* gb = B2 + (size_t)(n0 + r) * K2 + k0 + j * 8;
        cpa16(sbase + 2 * MATB + sw, gb);
        cpa16(sbase + 3 * MATB + sw, gb + CC);
    }
}

__global__ __launch_bounds__(256) void gemm_mma(
    const __nv_bfloat16* __restrict__ A2, const __nv_bfloat16* __restrict__ B2,
    const float* __restrict__ bias, float* __restrict__ C, int Nn)
{
    extern __shared__ char sm[];
    const uint32_t sb = smem_u32(sm);
    const int t = threadIdx.x, lane = t & 31, w = t >> 5;
    const int wm = (w >> 2) * 64, wn = (w & 3) * 32;
    const int m0 = blockIdx.y * GBM, n0 = blockIdx.x * GBN;

    const int lrow = lane & 15;           // ldmatrix source row within 16
    const int lcol = (lane >> 4) << 3;    // ldmatrix k-col select (0 or 8)

    float acc[4][4][4];
#pragma unroll
    for (int i = 0; i < 4; i++)
#pragma unroll
        for (int j = 0; j < 4; j++)
#pragma unroll
            for (int r = 0; r < 4; r++) acc[i][j][r] = 0.f;

    // double-buffered fragments
    uint32_t ah[2][4][4], al[2][4][4], bh[2][4][2], bl[2][4][2];

    // fragment loader for k-substep offset kb (0,16,32,48) into buffer bf
#define LDFR(bf, st, kb)                                                            \
    do {                                                                            \
        _Pragma("unroll")                                                           \
        for (int mi = 0; mi < 4; mi++) {                                            \
            uint32_t off = (wm + mi * 16 + lrow) * 128 + ((kb) + lcol) * 2;         \
            uint32_t sw = SW128(off);                                               \
            ldsm4(ah[bf][mi], (st) + sw);                                           \
            ldsm4(al[bf][mi], (st) + MATB + sw);                                    \
        }                                                                           \
        _Pragma("unroll")                                                           \
        for (int bj = 0; bj < 2; bj++) {                                            \
            uint32_t r4[4], s4[4];                                                  \
            uint32_t off = (wn + bj * 16 + lrow) * 128 + ((kb) + lcol) * 2;         \
            uint32_t sw = SW128(off);                                               \
            ldsm4(r4, (st) + 2 * MATB + sw);                                        \
            ldsm4(s4, (st) + 3 * MATB + sw);                                        \
            bh[bf][2 * bj + 0][0] = r4[0]; bh[bf][2 * bj + 0][1] = r4[2];           \
            bh[bf][2 * bj + 1][0] = r4[1]; bh[bf][2 * bj + 1][1] = r4[3];           \
            bl[bf][2 * bj + 0][0] = s4[0]; bl[bf][2 * bj + 0][1] = s4[2];           \
            bl[bf][2 * bj + 1][0] = s4[1]; bl[bf][2 * bj + 1][1] = s4[3];           \
        }                                                                           \
    } while (0)

    // prologue: chunks 0,1 into stages 0,1
    g2s_chunk(sb, A2, B2, m0, n0, 0, t);
    asm volatile("cp.async.commit_group;" ::: "memory");
    g2s_chunk(sb + STG, A2, B2, m0, n0, GBK, t);
    asm volatile("cp.async.commit_group;" ::: "memory");

    int stage = 0, wstage = 2;
    for (int c = 0; c < NCH; c++) {
        if (c == NCH - 1) asm volatile("cp.async.wait_group 0;" ::: "memory");
        else              asm volatile("cp.async.wait_group 1;" ::: "memory");
        __syncthreads();
        const uint32_t st = sb + stage * STG;
        stage = stage == 2 ? 0 : stage + 1;

        LDFR(0, st, 0);
#pragma unroll
        for (int ks = 0; ks < 4; ks++) {
            const int cur = ks & 1, nxt = cur ^ 1;
            if (ks < 3) {
                LDFR(nxt, st, (ks + 1) * 16);       // prefetch next substep's frags
            } else if (c + 2 < NCH) {
                // deferred gmem prefetch of chunk c+2 (hidden under this ks's MMAs)
                g2s_chunk(sb + wstage * STG, A2, B2, m0, n0, (c + 2) * GBK, t);
                asm volatile("cp.async.commit_group;" ::: "memory");
                wstage = wstage == 2 ? 0 : wstage + 1;
            }
            // 3 product passes; consecutive MMAs hit independent accumulators
#pragma unroll
            for (int mi = 0; mi < 4; mi++)
#pragma unroll
                for (int nj = 0; nj < 4; nj++)
                    mma_bf16(acc[mi][nj], ah[cur][mi], bh[cur][nj]);
#pragma unroll
            for (int mi = 0; mi < 4; mi++)
#pragma unroll
                for (int nj = 0; nj < 4; nj++)
                    mma_bf16(acc[mi][nj], al[cur][mi], bh[cur][nj]);
#pragma unroll
            for (int mi = 0; mi < 4; mi++)
#pragma unroll
                for (int nj = 0; nj < 4; nj++)
                    mma_bf16(acc[mi][nj], ah[cur][mi], bl[cur][nj]);
        }
    }

    // epilogue
    const int group = lane >> 2, tig = lane & 3;
#pragma unroll
    for (int mi = 0; mi < 4; mi++)
#pragma unroll
        for (int nj = 0; nj < 4; nj++) {
            int r0 = m0 + wm + mi * 16 + group;
            int cc0 = n0 + wn + nj * 8 + tig * 2;
            float b0 = 0.f, b1 = 0.f;
            if (bias) { b0 = bias[cc0]; b1 = bias[cc0 + 1]; }
            float2 v0 = make_float2(acc[mi][nj][0] + b0, acc[mi][nj][1] + b1);
            float2 v1 = make_float2(acc[mi][nj][2] + b0, acc[mi][nj][3] + b1);
            *(float2*)(C + (size_t)r0 * Nn + cc0)       = v0;
            *(float2*)(C + (size_t)(r0 + 8) * Nn + cc0) = v1;
        }
}

// ============================ split f32 -> (hi|lo) bf16 ==========================
__global__ __launch_bounds__(256) void split_kernel(
    const float* __restrict__ in, __nv_bfloat16* __restrict__ out, int rows)
{
    size_t idx = (size_t)blockIdx.x * 256 + threadIdx.x;
    size_t row = idx >> 8;
    if (row >= (size_t)rows) return;
    int c4 = (int)(idx & 255) << 2;
    float4 v = *(const float4*)(in + row * CC + c4);
    float vv[4] = {v.x, v.y, v.z, v.w};
    __nv_bfloat16 hb[4], lb[4];
#pragma unroll
    for (int j = 0; j < 4; j++) {
        hb[j] = __float2bfloat16(vv[j]);
        lb[j] = __float2bfloat16(vv[j] - __bfloat162float(hb[j]));
    }
    *(uint64_t*)(out + row * K2 + c4)      = *(uint64_t*)hb;
    *(uint64_t*)(out + row * K2 + CC + c4) = *(uint64_t*)lb;
}

// ================================== focus ========================================
__global__ __launch_bounds__(256) void focus_kernel(
    const float* __restrict__ scale, const float* __restrict__ pos_enc)
{
    const int row = blockIdx.x;
    const int n = row & (SEQ - 1);
    float* qp = g_qkv + (size_t)row * C3;
    float* kp = qp + CC;
    const int t = threadIdx.x;
    const int c0 = t * 4;

    float4 q4 = *(float4*)(qp + c0);
    float4 k4 = *(float4*)(kp + c0);
    const float4 pe  = *(const float4*)(pos_enc + (size_t)n * CC + c0);
    const float4 sc4 = *(const float4*)(scale + c0);

    float qv[4] = {q4.x, q4.y, q4.z, q4.w};
    float kv[4] = {k4.x + pe.x, k4.y + pe.y, k4.z + pe.z, k4.w + pe.w};
    float sv[4] = {sc4.x, sc4.y, sc4.z, sc4.w};

    float s2q = 0.f, s6q = 0.f, s2k = 0.f, s6k = 0.f;
#pragma unroll
    for (int j = 0; j < 4; j++) {
        float sc = log1pf(expf(sv[j]));
        float q = (fmaxf(qv[j], 0.f) + EPS) / sc;
        float k = (fmaxf(kv[j], 0.f) + EPS) / sc;
        qv[j] = q; kv[j] = k;
        float q2 = q * q, k2 = k * k;
        s2q += q2; s2k += k2;
        float q3 = q2 * q, k3 = k2 * k;
        s6q += q3 * q3; s6k += k3 * k3;
    }
    __shared__ float red[8][4];
    const int lid = t & 31, wid = t >> 5;
#pragma unroll
    for (int o = 16; o > 0; o >>= 1) {
        s2q += __shfl_xor_sync(0xffffffffu, s2q, o);
        s6q += __shfl_xor_sync(0xffffffffu, s6q, o);
        s2k += __shfl_xor_sync(0xffffffffu, s2k, o);
        s6k += __shfl_xor_sync(0xffffffffu, s6k, o);
    }
    if (lid == 0) { red[wid][0] = s2q; red[wid][1] = s6q; red[wid][2] = s2k; red[wid][3] = s6k; }
    __syncthreads();
    float t2q = 0.f, t6q = 0.f, t2k = 0.f, t6k = 0.f;
#pragma unroll
    for (int wq = 0; wq < 8; wq++) {
        t2q += red[wq][0]; t6q += red[wq][1]; t2k += red[wq][2]; t6k += red[wq][3];
    }
    const float fq = sqrtf(t2q / t6q);
    const float fk = sqrtf(t2k / t6k);

    float4 qo, ko;
    float* qvo = (float*)&qo; float* kvo = (float*)&ko;
#pragma unroll
    for (int j = 0; j < 4; j++) {
        qvo[j] = qv[j] * qv[j] * qv[j] * fq;
        kvo[j] = kv[j] * kv[j] * kv[j] * fk;
    }
    *(float4*)(qp + c0) = qo;
    *(float4*)(kp + c0) = ko;
}

__global__ void zero_kv_kernel()
{
    int i = blockIdx.x * 256 + threadIdx.x;
    if (i < BH * DD * DD) g_kv[i] = 0.f;
    if (i < BH * DD)      g_ksum[i] = 0.f;
}

// ==================================== kv =========================================
#define NSPLIT 8
#define NCHUNK (SEQ / NSPLIT)
__global__ __launch_bounds__(64) void kv_kernel()
{
    const int bh = blockIdx.x;
    const int sp = blockIdx.y;
    const int b = bh >> 4, h = bh & 15;
    const int n0 = sp * NCHUNK;
    __shared__ float ks[32][64];
    __shared__ float vs[32][64];
    const int t = threadIdx.x;
    const int tc = (t >> 3) << 3;
    const int td = (t & 7) << 3;
    unsigned long long acc2[8][4];
#pragma unroll
    for (int i = 0; i < 8; i++)
#pragma unroll
        for (int j = 0; j < 4; j++) acc2[i][j] = 0ULL;
    float ksacc = 0.f;

    for (int nt = 0; nt < NCHUNK; nt += 32) {
#pragma unroll
        for (int l = 0; l < 8; l++) {
            int idx4 = t + l * 64;
            int nn = idx4 >> 4, q4 = (idx4 & 15) << 2;
            size_t base = ((size_t)(b * SEQ + n0 + nt + nn)) * C3 + h * DD + q4;
            *(float4*)&ks[nn][q4] = *(const float4*)&g_qkv[base + CC];
            *(float4*)&vs[nn][q4] = *(const float4*)&g_qkv[base + 2 * CC];
        }
        __syncthreads();
#pragma unroll 4
        for (int nn = 0; nn < 32; nn++) {
            float a[8];
            *(float4*)(a)      = *(float4*)&ks[nn][tc];
            *(float4*)(a + 4)  = *(float4*)&ks[nn][tc + 4];
            unsigned long long b2[4];
            *(ulonglong2*)(b2)     = *(const ulonglong2*)(&vs[nn][td]);
            *(ulonglong2*)(b2 + 2) = *(const ulonglong2*)(&vs[nn][td + 4]);
#pragma unroll
            for (int i = 0; i < 8; i++) {
                unsigned long long a2;
                asm("mov.b64 %0, {%1, %1};" : "=l"(a2) : "f"(a[i]));
#pragma unroll
                for (int j = 0; j < 4; j++)
                    asm("fma.rn.f32x2 %0, %1, %2, %0;" : "+l"(acc2[i][j]) : "l"(a2), "l"(b2[j]));
            }
            ksacc += ks[nn][t];
        }
        __syncthreads();
    }
#pragma unroll
    for (int i = 0; i < 8; i++)
#pragma unroll
        for (int j = 0; j < 4; j++) {
            float lo, hi;
            asm("mov.b64 {%0, %1}, %2;" : "=f"(lo), "=f"(hi) : "l"(acc2[i][j]));
            atomicAdd(&g_kv[((size_t)bh * DD + tc + i) * DD + td + 2 * j], lo);
            atomicAdd(&g_kv[((size_t)bh * DD + tc + i) * DD + td + 2 * j + 1], hi);
        }
    atomicAdd(&g_ksum[bh * DD + t], ksacc);
}

// ============ o kernel: writes split bf16 (hi|lo) directly into g_o2 =============
__global__ __launch_bounds__(256) void o_kernel()
{
    const int bh = blockIdx.x;
    const int ic = blockIdx.y;
    const int b = bh >> 4, h = bh & 15;
    const int i0 = ic * 64;
    __shared__ float qs[64][68];
    __shared__ float kvs[64][64];
    __shared__ float ks_s[64];
    __shared__ float z_s[64];
    const int t = threadIdx.x;

    for (int idx = t; idx < DD * DD; idx += 256)
        kvs[idx >> 6][idx & 63] = g_kv[(size_t)bh * DD * DD + idx];
    if (t < 64) ks_s[t] = g_ksum[bh * DD + t];
    for (int idx = t; idx < 64 * 64; idx += 256) {
        int r = idx >> 6, c = idx & 63;
        qs[c][r] = g_qkv[((size_t)(b * SEQ + i0 + r)) * C3 + h * DD + c];
    }
    __syncthreads();

    if (t < 64) {
        float s = 0.f;
#pragma unroll 8
        for (int c = 0; c < 64; c++) s += qs[c][t] * ks_s[c];
        z_s[t] = 1.0f / (s + EPS);
    }
    __syncthreads();

    const int tm = (t >> 5) << 3;
    const int tn = (t & 31) << 1;
    float acc[8][2] = {};
#pragma unroll 8
    for (int c = 0; c < 64; c++) {
        float a[8];
        *(float4*)(a)     = *(float4*)&qs[c][tm];
        *(float4*)(a + 4) = *(float4*)&qs[c][tm + 4];
        float2 bv = *(float2*)&kvs[c][tn];
#pragma unroll
        for (int i = 0; i < 8; i++) {
            acc[i][0] += a[i] * bv.x;
            acc[i][1] += a[i] * bv.y;
        }
    }
#pragma unroll
    for (int i = 0; i < 8; i++) {
        float z = z_s[tm + i];
        float v0 = acc[i][0] * z, v1 = acc[i][1] * z;
        __nv_bfloat16 hb0 = __float2bfloat16(v0), hb1 = __float2bfloat16(v1);
        __nv_bfloat16 lb0 = __float2bfloat16(v0 - __bfloat162float(hb0));
        __nv_bfloat16 lb1 = __float2bfloat16(v1 - __bfloat162float(hb1));
        size_t off = ((size_t)(b * SEQ + i0 + tm + i)) * K2 + h * DD + tn;
        __nv_bfloat162 hp; hp.x = hb0; hp.y = hb1;
        __nv_bfloat162 lp; lp.x = lb0; lp.y = lb1;
        *(__nv_bfloat162*)(g_o2 + off)      = hp;
        *(__nv_bfloat162*)(g_o2 + off + CC) = lp;
    }
}

// =================================================================================
extern "C" void kernel_launch(void* const* d_in, const int* in_sizes, int n_in,
                              void* d_out, int out_size)
{
    const float* x       = (const float*)d_in[0];
    const float* scale   = (const float*)d_in[1];
    const float* pos_enc = (const float*)d_in[2];
    const float* qkv_w   = (const float*)d_in[3];
    const float* proj_w  = (const float*)d_in[4];
    const float* proj_b  = (const float*)d_in[5];
    float* out = (float*)d_out;

    float *qkv_p = nullptr;
    __nv_bfloat16 *x2_p = nullptr, *o2_p = nullptr, *wq2_p = nullptr, *wp2_p = nullptr;
    cudaGetSymbolAddress((void**)&qkv_p, g_qkv);
    cudaGetSymbolAddress((void**)&x2_p, g_x2);
    cudaGetSymbolAddress((void**)&o2_p, g_o2);
    cudaGetSymbolAddress((void**)&wq2_p, g_wq2);
    cudaGetSymbolAddress((void**)&wp2_p, g_wp2);

    cudaFuncSetAttribute(gemm_mma, cudaFuncAttributeMaxDynamicSharedMemorySize, GSMEM);

    // 0) bf16 splits of x and weights
    split_kernel<<<MM, 256>>>(x, x2_p, MM);
    split_kernel<<<C3, 256>>>(qkv_w, wq2_p, C3);
    split_kernel<<<CC, 256>>>(proj_w, wp2_p, CC);
    // 1) qkv = x @ qkv_w^T  (HMMA, bf16-split, fp32 accumulate)
    gemm_mma<<<dim3(C3 / GBN, MM / GBM), 256, GSMEM>>>(x2_p, wq2_p, nullptr, qkv_p, C3);
    // 2) focusing / activation (in-place on q,k)
    focus_kernel<<<MM, 256>>>(scale, pos_enc);
    // 3) kv = k^T v (+ ksum)
    zero_kv_kernel<<<(BH * DD * DD + 255) / 256, 256>>>();
    kv_kernel<<<dim3(BH, NSPLIT), 64>>>();
    // 4) o = z * (q @ kv), written as split bf16 in merged-head layout
    o_kernel<<<dim3(BH, SEQ / 64), 256>>>();
    // 5) out = o @ proj_w^T + proj_b  (HMMA)
    gemm_mma<<<dim3(CC / GBN, MM / GBM), 256, GSMEM>>>(o2_p, wp2_p, proj_b, out, CC);
}

// round 9
// speedup vs baseline: 1.5686x; 1.0165x over previous
#include <cuda_runtime.h>
#include <cuda_bf16.h>
#include <cstdint>
#include <cstddef>

// Problem constants
#define BB 8
#define SEQ 4096
#define CC 1024
#define HH 16
#define DD 64
#define MM (BB*SEQ)          // 32768
#define C3 (3*CC)            // 3072
#define BH (BB*HH)           // 128
#define EPS 1e-6f
#define K2 2048              // split operand width (hi | lo)

// ---------------- scratch (device globals; no allocation allowed) ----------------
__device__ float g_qkv[(size_t)MM * C3];          // q | k | v  (f32, focus in-place)
__device__ float g_kv[(size_t)BH * DD * DD];
__device__ float g_ksum[BH * DD];
__device__ __nv_bfloat16 g_x2[(size_t)MM * K2];   // x split   [M][hi(1024)|lo(1024)]
__device__ __nv_bfloat16 g_o2[(size_t)MM * K2];   // o split
__device__ __nv_bfloat16 g_wq2[(size_t)C3 * K2];  // qkv_w split
__device__ __nv_bfloat16 g_wp2[(size_t)CC * K2];  // proj_w split

// ================================ helpers ========================================
__device__ __forceinline__ uint32_t smem_u32(const void* p) {
    uint32_t a;
    asm("{ .reg .u64 t; cvta.to.shared.u64 t, %1; cvt.u32.u64 %0, t; }" : "=r"(a) : "l"(p));
    return a;
}
__device__ __forceinline__ void cpa16(uint32_t sa, const void* g) {
    size_t ga = __cvta_generic_to_global(g);
    asm volatile("cp.async.cg.shared.global [%0], [%1], 16;" :: "r"(sa), "l"(ga) : "memory");
}
__device__ __forceinline__ void ldsm4(uint32_t* d, uint32_t addr) {
    asm volatile("ldmatrix.sync.aligned.m8n8.x4.shared.b16 {%0,%1,%2,%3}, [%4];"
        : "=r"(d[0]), "=r"(d[1]), "=r"(d[2]), "=r"(d[3]) : "r"(addr));
}
__device__ __forceinline__ void mma_bf16(float* c, const uint32_t* a, const uint32_t* b) {
    asm volatile("mma.sync.aligned.m16n8k16.row.col.f32.bf16.bf16.f32 "
        "{%0,%1,%2,%3}, {%4,%5,%6,%7}, {%8,%9}, {%0,%1,%2,%3};"
        : "+f"(c[0]), "+f"(c[1]), "+f"(c[2]), "+f"(c[3])
        : "r"(a[0]), "r"(a[1]), "r"(a[2]), "r"(a[3]), "r"(b[0]), "r"(b[1]));
}
// 64B-row swizzle: XOR col16 (bits[5:4]) with row bits[2:1] (off bits [8:7]).
// Every ldmatrix 8-row phase then touches 8 disjoint 4-bank groups.
#define SW64R(o) ((o) ^ (((o) >> 3) & 0x30))

// ============================ HMMA split GEMM ====================================
// C[m,n] = sum_k A[m,k]*B[n,k] (fp32 via bf16 split: Ah*Bh + Al*Bh + Ah*Bl)
// BM=128, BN=128, BK=32; 256 threads; warp tile 64x32 (2x4); 3-stage cp.async;
// 2 CTAs/SM (96KB smem, <=128 regs via launch_bounds).
#define GBM 128
#define GBN 128
#define GBK 32
#define NCH (CC / GBK)          // 32 k-chunks
#define MATB (128 * 64)         // 8192 B per matrix tile (128 rows x 64B)
#define STG (4 * MATB)          // Ah|Al|Bh|Bl = 32768 B per stage
#define NSTG 3
#define GSMEM (NSTG * STG)      // 98304 B -> 2 CTAs/SM

__device__ __forceinline__ void g2s_chunk(uint32_t sbase,
    const __nv_bfloat16* __restrict__ A2, const __nv_bfloat16* __restrict__ B2,
    int m0, int n0, int k0, int t)
{
#pragma unroll
    for (int i = 0; i < 2; i++) {
        int idx = t + i * 256;            // 512 16B-chunks per matrix
        int r = idx >> 2, j = idx & 3;
        uint32_t off = r * 64 + j * 16;
        uint32_t sw = SW64R(off);
        const __nv_bfloat16* ga = A2 + (size_t)(m0 + r) * K2 + k0 + j * 8;
        cpa16(sbase + 0 * MATB + sw, ga);
        cpa16(sbase + 1 * MATB + sw, ga + CC);
        const __nv_bfloat16* gb = B2 + (size_t)(n0 + r) * K2 + k0 + j * 8;
        cpa16(sbase + 2 * MATB + sw, gb);
        cpa16(sbase + 3 * MATB + sw, gb + CC);
    }
}

__global__ __launch_bounds__(256, 2) void gemm_mma(
    const __nv_bfloat16* __restrict__ A2, const __nv_bfloat16* __restrict__ B2,
    const float* __restrict__ bias, float* __restrict__ C, int Nn)
{
    extern __shared__ char sm[];
    const uint32_t sb = smem_u32(sm);
    const int t = threadIdx.x, lane = t & 31, w = t >> 5;
    const int wm = (w >> 2) * 64, wn = (w & 3) * 32;
    const int m0 = blockIdx.y * GBM, n0 = blockIdx.x * GBN;

    const int lrow = lane & 15;           // ldmatrix source row within 16
    const int lcol = (lane >> 4) << 3;    // ldmatrix k-col select (0 or 8)

    float acc[4][4][4];
#pragma unroll
    for (int i = 0; i < 4; i++)
#pragma unroll
        for (int j = 0; j < 4; j++)
#pragma unroll
            for (int r = 0; r < 4; r++) acc[i][j][r] = 0.f;

    // A-fragment loader (4x ldsm4) at byte col (kb+lcol)*2 from matrix base mb
#define LDA(fr, mb, kb)                                                             \
    do {                                                                            \
        _Pragma("unroll")                                                           \
        for (int mi = 0; mi < 4; mi++) {                                            \
            uint32_t off = (wm + mi * 16 + lrow) * 64 + ((kb) + lcol) * 2;          \
            ldsm4(fr[mi], (mb) + SW64R(off));                                       \
        }                                                                           \
    } while (0)
    // B-fragment loader (2x ldsm4 -> 4 n-tiles of 2 regs)
#define LDB(fr, mb, kb)                                                             \
    do {                                                                            \
        _Pragma("unroll")                                                           \
        for (int bj = 0; bj < 2; bj++) {                                            \
            uint32_t r4[4];                                                         \
            uint32_t off = (wn + bj * 16 + lrow) * 64 + ((kb) + lcol) * 2;          \
            ldsm4(r4, (mb) + SW64R(off));                                           \
            fr[2 * bj + 0][0] = r4[0]; fr[2 * bj + 0][1] = r4[2];                   \
            fr[2 * bj + 1][0] = r4[1]; fr[2 * bj + 1][1] = r4[3];                   \
        }                                                                           \
    } while (0)
#define MPASS(af, bf)                                                               \
    do {                                                                            \
        _Pragma("unroll")                                                           \
        for (int mi = 0; mi < 4; mi++)                                              \
            _Pragma("unroll")                                                       \
            for (int nj = 0; nj < 4; nj++)                                          \
                mma_bf16(acc[mi][nj], af[mi], bf[nj]);                              \
    } while (0)

    // prologue: chunks 0,1 into stages 0,1
    g2s_chunk(sb, A2, B2, m0, n0, 0, t);
    asm volatile("cp.async.commit_group;" ::: "memory");
    g2s_chunk(sb + STG, A2, B2, m0, n0, GBK, t);
    asm volatile("cp.async.commit_group;" ::: "memory");

    int stage = 0, wstage = 2;
    for (int c = 0; c < NCH; c++) {
        if (c == NCH - 1) asm volatile("cp.async.wait_group 0;" ::: "memory");
        else              asm volatile("cp.async.wait_group 1;" ::: "memory");
        __syncthreads();
        if (c + 2 < NCH) {
            g2s_chunk(sb + wstage * STG, A2, B2, m0, n0, (c + 2) * GBK, t);
            asm volatile("cp.async.commit_group;" ::: "memory");
            wstage = wstage == 2 ? 0 : wstage + 1;
        }
        const uint32_t st = sb + stage * STG;
        stage = stage == 2 ? 0 : stage + 1;

#pragma unroll
        for (int ks = 0; ks < 2; ks++) {
            const int kb = ks * 16;
            uint32_t ah[4][4], bh[4][2];
            LDA(ah, st, kb);
            LDB(bh, st + 2 * MATB, kb);
            MPASS(ah, bh);                    // Ah*Bh
            {
                uint32_t al[4][4];
                LDA(al, st + MATB, kb);
                MPASS(al, bh);                // Al*Bh
            }
            {
                uint32_t bl[4][2];
                LDB(bl, st + 3 * MATB, kb);
                MPASS(ah, bl);                // Ah*Bl
            }
        }
    }

    // epilogue
    const int group = lane >> 2, tig = lane & 3;
#pragma unroll
    for (int mi = 0; mi < 4; mi++)
#pragma unroll
        for (int nj = 0; nj < 4; nj++) {
            int r0 = m0 + wm + mi * 16 + group;
            int cc0 = n0 + wn + nj * 8 + tig * 2;
            float b0 = 0.f, b1 = 0.f;
            if (bias) { b0 = bias[cc0]; b1 = bias[cc0 + 1]; }
            float2 v0 = make_float2(acc[mi][nj][0] + b0, acc[mi][nj][1] + b1);
            float2 v1 = make_float2(acc[mi][nj][2] + b0, acc[mi][nj][3] + b1);
            *(float2*)(C + (size_t)r0 * Nn + cc0)       = v0;
            *(float2*)(C + (size_t)(r0 + 8) * Nn + cc0) = v1;
        }
}

// ============================ split f32 -> (hi|lo) bf16 ==========================
__global__ __launch_bounds__(256) void split_kernel(
    const float* __restrict__ in, __nv_bfloat16* __restrict__ out, int rows)
{
    size_t idx = (size_t)blockIdx.x * 256 + threadIdx.x;
    size_t row = idx >> 8;
    if (row >= (size_t)rows) return;
    int c4 = (int)(idx & 255) << 2;
    float4 v = *(const float4*)(in + row * CC + c4);
    float vv[4] = {v.x, v.y, v.z, v.w};
    __nv_bfloat16 hb[4], lb[4];
#pragma unroll
    for (int j = 0; j < 4; j++) {
        hb[j] = __float2bfloat16(vv[j]);
        lb[j] = __float2bfloat16(vv[j] - __bfloat162float(hb[j]));
    }
    *(uint64_t*)(out + row * K2 + c4)      = *(uint64_t*)hb;
    *(uint64_t*)(out + row * K2 + CC + c4) = *(uint64_t*)lb;
}

// ================================== focus ========================================
__global__ __launch_bounds__(256) void focus_kernel(
    const float* __restrict__ scale, const float* __restrict__ pos_enc)
{
    const int row = blockIdx.x;
    const int n = row & (SEQ - 1);
    float* qp = g_qkv + (size_t)row * C3;
    float* kp = qp + CC;
    const int t = threadIdx.x;
    const int c0 = t * 4;

    float4 q4 = *(float4*)(qp + c0);
    float4 k4 = *(float4*)(kp + c0);
    const float4 pe  = *(const float4*)(pos_enc + (size_t)n * CC + c0);
    const float4 sc4 = *(const float4*)(scale + c0);

    float qv[4] = {q4.x, q4.y, q4.z, q4.w};
    float kv[4] = {k4.x + pe.x, k4.y + pe.y, k4.z + pe.z, k4.w + pe.w};
    float sv[4] = {sc4.x, sc4.y, sc4.z, sc4.w};

    float s2q = 0.f, s6q = 0.f, s2k = 0.f, s6k = 0.f;
#pragma unroll
    for (int j = 0; j < 4; j++) {
        float sc = log1pf(expf(sv[j]));
        float q = (fmaxf(qv[j], 0.f) + EPS) / sc;
        float k = (fmaxf(kv[j], 0.f) + EPS) / sc;
        qv[j] = q; kv[j] = k;
        float q2 = q * q, k2 = k * k;
        s2q += q2; s2k += k2;
        float q3 = q2 * q, k3 = k2 * k;
        s6q += q3 * q3; s6k += k3 * k3;
    }
    __shared__ float red[8][4];
    const int lid = t & 31, wid = t >> 5;
#pragma unroll
    for (int o = 16; o > 0; o >>= 1) {
        s2q += __shfl_xor_sync(0xffffffffu, s2q, o);
        s6q += __shfl_xor_sync(0xffffffffu, s6q, o);
        s2k += __shfl_xor_sync(0xffffffffu, s2k, o);
        s6k += __shfl_xor_sync(0xffffffffu, s6k, o);
    }
    if (lid == 0) { red[wid][0] = s2q; red[wid][1] = s6q; red[wid][2] = s2k; red[wid][3] = s6k; }
    __syncthreads();
    float t2q = 0.f, t6q = 0.f, t2k = 0.f, t6k = 0.f;
#pragma unroll
    for (int wq = 0; wq < 8; wq++) {
        t2q += red[wq][0]; t6q += red[wq][1]; t2k += red[wq][2]; t6k += red[wq][3];
    }
    const float fq = sqrtf(t2q / t6q);
    const float fk = sqrtf(t2k / t6k);

    float4 qo, ko;
    float* qvo = (float*)&qo; float* kvo = (float*)&ko;
#pragma unroll
    for (int j = 0; j < 4; j++) {
        qvo[j] = qv[j] * qv[j] * qv[j] * fq;
        kvo[j] = kv[j] * kv[j] * kv[j] * fk;
    }
    *(float4*)(qp + c0) = qo;
    *(float4*)(kp + c0) = ko;
}

__global__ void zero_kv_kernel()
{
    int i = blockIdx.x * 256 + threadIdx.x;
    if (i < BH * DD * DD) g_kv[i] = 0.f;
    if (i < BH * DD)      g_ksum[i] = 0.f;
}

// ==================================== kv =========================================
#define NSPLIT 8
#define NCHUNK (SEQ / NSPLIT)
__global__ __launch_bounds__(64) void kv_kernel()
{
    const int bh = blockIdx.x;
    const int sp = blockIdx.y;
    const int b = bh >> 4, h = bh & 15;
    const int n0 = sp * NCHUNK;
    __shared__ float ks[32][64];
    __shared__ float vs[32][64];
    const int t = threadIdx.x;
    const int tc = (t >> 3) << 3;
    const int td = (t & 7) << 3;
    unsigned long long acc2[8][4];
#pragma unroll
    for (int i = 0; i < 8; i++)
#pragma unroll
        for (int j = 0; j < 4; j++) acc2[i][j] = 0ULL;
    float ksacc = 0.f;

    for (int nt = 0; nt < NCHUNK; nt += 32) {
#pragma unroll
        for (int l = 0; l < 8; l++) {
            int idx4 = t + l * 64;
            int nn = idx4 >> 4, q4 = (idx4 & 15) << 2;
            size_t base = ((size_t)(b * SEQ + n0 + nt + nn)) * C3 + h * DD + q4;
            *(float4*)&ks[nn][q4] = *(const float4*)&g_qkv[base + CC];
            *(float4*)&vs[nn][q4] = *(const float4*)&g_qkv[base + 2 * CC];
        }
        __syncthreads();
#pragma unroll 4
        for (int nn = 0; nn < 32; nn++) {
            float a[8];
            *(float4*)(a)      = *(float4*)&ks[nn][tc];
            *(float4*)(a + 4)  = *(float4*)&ks[nn][tc + 4];
            unsigned long long b2[4];
            *(ulonglong2*)(b2)     = *(const ulonglong2*)(&vs[nn][td]);
            *(ulonglong2*)(b2 + 2) = *(const ulonglong2*)(&vs[nn][td + 4]);
#pragma unroll
            for (int i = 0; i < 8; i++) {
                unsigned long long a2;
                asm("mov.b64 %0, {%1, %1};" : "=l"(a2) : "f"(a[i]));
#pragma unroll
                for (int j = 0; j < 4; j++)
                    asm("fma.rn.f32x2 %0, %1, %2, %0;" : "+l"(acc2[i][j]) : "l"(a2), "l"(b2[j]));
            }
            ksacc += ks[nn][t];
        }
        __syncthreads();
    }
#pragma unroll
    for (int i = 0; i < 8; i++)
#pragma unroll
        for (int j = 0; j < 4; j++) {
            float lo, hi;
            asm("mov.b64 {%0, %1}, %2;" : "=f"(lo), "=f"(hi) : "l"(acc2[i][j]));
            atomicAdd(&g_kv[((size_t)bh * DD + tc + i) * DD + td + 2 * j], lo);
            atomicAdd(&g_kv[((size_t)bh * DD + tc + i) * DD + td + 2 * j + 1], hi);
        }
    atomicAdd(&g_ksum[bh * DD + t], ksacc);
}

// ============ o kernel: writes split bf16 (hi|lo) directly into g_o2 =============
__global__ __launch_bounds__(256) void o_kernel()
{
    const int bh = blockIdx.x;
    const int ic = blockIdx.y;
    const int b = bh >> 4, h = bh & 15;
    const int i0 = ic * 64;
    __shared__ float qs[64][68];
    __shared__ float kvs[64][64];
    __shared__ float ks_s[64];
    __shared__ float z_s[64];
    const int t = threadIdx.x;

    for (int idx = t; idx < DD * DD; idx += 256)
        kvs[idx >> 6][idx & 63] = g_kv[(size_t)bh * DD * DD + idx];
    if (t < 64) ks_s[t] = g_ksum[bh * DD + t];
    for (int idx = t; idx < 64 * 64; idx += 256) {
        int r = idx >> 6, c = idx & 63;
        qs[c][r] = g_qkv[((size_t)(b * SEQ + i0 + r)) * C3 + h * DD + c];
    }
    __syncthreads();

    if (t < 64) {
        float s = 0.f;
#pragma unroll 8
        for (int c = 0; c < 64; c++) s += qs[c][t] * ks_s[c];
        z_s[t] = 1.0f / (s + EPS);
    }
    __syncthreads();

    const int tm = (t >> 5) << 3;
    const int tn = (t & 31) << 1;
    float acc[8][2] = {};
#pragma unroll 8
    for (int c = 0; c < 64; c++) {
        float a[8];
        *(float4*)(a)     = *(float4*)&qs[c][tm];
        *(float4*)(a + 4) = *(float4*)&qs[c][tm + 4];
        float2 bv = *(float2*)&kvs[c][tn];
#pragma unroll
        for (int i = 0; i < 8; i++) {
            acc[i][0] += a[i] * bv.x;
            acc[i][1] += a[i] * bv.y;
        }
    }
#pragma unroll
    for (int i = 0; i < 8; i++) {
        float z = z_s[tm + i];
        float v0 = acc[i][0] * z, v1 = acc[i][1] * z;
        __nv_bfloat16 hb0 = __float2bfloat16(v0), hb1 = __float2bfloat16(v1);
        __nv_bfloat16 lb0 = __float2bfloat16(v0 - __bfloat162float(hb0));
        __nv_bfloat16 lb1 = __float2bfloat16(v1 - __bfloat162float(hb1));
        size_t off = ((size_t)(b * SEQ + i0 + tm + i)) * K2 + h * DD + tn;
        __nv_bfloat162 hp; hp.x = hb0; hp.y = hb1;
        __nv_bfloat162 lp; lp.x = lb0; lp.y = lb1;
        *(__nv_bfloat162*)(g_o2 + off)      = hp;
        *(__nv_bfloat162*)(g_o2 + off + CC) = lp;
    }
}

// =================================================================================
extern "C" void kernel_launch(void* const* d_in, const int* in_sizes, int n_in,
                              void* d_out, int out_size)
{
    const float* x       = (const float*)d_in[0];
    const float* scale   = (const float*)d_in[1];
    const float* pos_enc = (const float*)d_in[2];
    const float* qkv_w   = (const float*)d_in[3];
    const float* proj_w  = (const float*)d_in[4];
    const float* proj_b  = (const float*)d_in[5];
    float* out = (float*)d_out;

    float *qkv_p = nullptr;
    __nv_bfloat16 *x2_p = nullptr, *o2_p = nullptr, *wq2_p = nullptr, *wp2_p = nullptr;
    cudaGetSymbolAddress((void**)&qkv_p, g_qkv);
    cudaGetSymbolAddress((void**)&x2_p, g_x2);
    cudaGetSymbolAddress((void**)&o2_p, g_o2);
    cudaGetSymbolAddress((void**)&wq2_p, g_wq2);
    cudaGetSymbolAddress((void**)&wp2_p, g_wp2);

    cudaFuncSetAttribute(gemm_mma, cudaFuncAttributeMaxDynamicSharedMemorySize, GSMEM);

    // 0) bf16 splits of x and weights
    split_kernel<<<MM, 256>>>(x, x2_p, MM);
    split_kernel<<<C3, 256>>>(qkv_w, wq2_p, C3);
    split_kernel<<<CC, 256>>>(proj_w, wp2_p, CC);
    // 1) qkv = x @ qkv_w^T  (HMMA, bf16-split, fp32 accumulate)
    gemm_mma<<<dim3(C3 / GBN, MM / GBM), 256, GSMEM>>>(x2_p, wq2_p, nullptr, qkv_p, C3);
    // 2) focusing / activation (in-place on q,k)
    focus_kernel<<<MM, 256>>>(scale, pos_enc);
    // 3) kv = k^T v (+ ksum)
    zero_kv_kernel<<<(BH * DD * DD + 255) / 256, 256>>>();
    kv_kernel<<<dim3(BH, NSPLIT), 64>>>();
    // 4) o = z * (q @ kv), written as split bf16 in merged-head layout
    o_kernel<<<dim3(BH, SEQ / 64), 256>>>();
    // 5) out = o @ proj_w^T + proj_b  (HMMA)
    gemm_mma<<<dim3(CC / GBN, MM / GBM), 256, GSMEM>>>(o2_p, wp2_p, proj_b, out, CC);
}

// round 10
// speedup vs baseline: 2.0658x; 1.3170x over previous
#include <cuda_runtime.h>
#include <cuda_bf16.h>
#include <cuda_fp16.h>
#include <cstdint>
#include <cstddef>

// Problem constants
#define BB 8
#define SEQ 4096
#define CC 1024
#define HH 16
#define DD 64
#define MM (BB*SEQ)          // 32768
#define C3 (3*CC)            // 3072
#define BH (BB*HH)           // 128
#define EPS 1e-6f
#define K2 2048              // split activation width (hi | lo)

// ---------------- scratch (device globals; no allocation allowed) ----------------
__device__ float g_qkv[(size_t)MM * C3];          // q | k | v  (f32, focus in-place)
__device__ float g_kv[(size_t)BH * DD * DD];
__device__ float g_ksum[BH * DD];
__device__ __half g_x2[(size_t)MM * K2];          // x split   [M][hi(1024)|lo(1024)]
__device__ __half g_o2[(size_t)MM * K2];          // o split
__device__ __half g_wqh[(size_t)C3 * CC];         // fp16(qkv_w)
__device__ __half g_wph[(size_t)CC * CC];         // fp16(proj_w)

// ================================ helpers ========================================
__device__ __forceinline__ uint32_t smem_u32(const void* p) {
    uint32_t a;
    asm("{ .reg .u64 t; cvta.to.shared.u64 t, %1; cvt.u32.u64 %0, t; }" : "=r"(a) : "l"(p));
    return a;
}
__device__ __forceinline__ void cpa16(uint32_t sa, const void* g) {
    size_t ga = __cvta_generic_to_global(g);
    asm volatile("cp.async.cg.shared.global [%0], [%1], 16;" :: "r"(sa), "l"(ga) : "memory");
}
__device__ __forceinline__ void ldsm4(uint32_t* d, uint32_t addr) {
    asm volatile("ldmatrix.sync.aligned.m8n8.x4.shared.b16 {%0,%1,%2,%3}, [%4];"
        : "=r"(d[0]), "=r"(d[1]), "=r"(d[2]), "=r"(d[3]) : "r"(addr));
}
__device__ __forceinline__ void mma_f16(float* c, const uint32_t* a, const uint32_t* b) {
    asm volatile("mma.sync.aligned.m16n8k16.row.col.f32.f16.f16.f32 "
        "{%0,%1,%2,%3}, {%4,%5,%6,%7}, {%8,%9}, {%0,%1,%2,%3};"
        : "+f"(c[0]), "+f"(c[1]), "+f"(c[2]), "+f"(c[3])
        : "r"(a[0]), "r"(a[1]), "r"(a[2]), "r"(a[3]), "r"(b[0]), "r"(b[1]));
}
// 64B-row swizzle: XOR col16 (bits[5:4]) with row bits[2:1] (off bits [8:7]).
#define SW64R(o) ((o) ^ (((o) >> 3) & 0x30))

// ============================ HMMA fp16x2 GEMM ===================================
// C[m,n] = sum_k A[m,k]*W[n,k];  A exact as fp16 hi+lo, W rounded to fp16.
// Two MMA passes: Ah*Wh + Al*Wh.  BM=128, BN=128, BK=32; 256 thr; warp 64x32;
// 4-stage cp.async; 2 CTAs/SM.
#define GBM 128
#define GBN 128
#define GBK 32
#define NCH (CC / GBK)          // 32 k-chunks
#define MATB (128 * 64)         // 8192 B per matrix tile (128 rows x 64B)
#define STG (3 * MATB)          // Ah|Al|Wh = 24576 B per stage
#define NSTG 4
#define GSMEM (NSTG * STG)      // 98304 B -> 2 CTAs/SM

__device__ __forceinline__ void g2s_chunk(uint32_t sbase,
    const __half* __restrict__ A2, const __half* __restrict__ Wh,
    int m0, int n0, int k0, int t)
{
#pragma unroll
    for (int i = 0; i < 2; i++) {
        int idx = t + i * 256;            // 512 16B-chunks per matrix
        int r = idx >> 2, j = idx & 3;
        uint32_t off = r * 64 + j * 16;
        uint32_t sw = SW64R(off);
        const __half* ga = A2 + (size_t)(m0 + r) * K2 + k0 + j * 8;
        cpa16(sbase + 0 * MATB + sw, ga);
        cpa16(sbase + 1 * MATB + sw, ga + CC);
        const __half* gb = Wh + (size_t)(n0 + r) * CC + k0 + j * 8;
        cpa16(sbase + 2 * MATB + sw, gb);
    }
}

__global__ __launch_bounds__(256, 2) void gemm_mma(
    const __half* __restrict__ A2, const __half* __restrict__ Wh,
    const float* __restrict__ bias, float* __restrict__ C, int Nn)
{
    extern __shared__ char sm[];
    const uint32_t sb = smem_u32(sm);
    const int t = threadIdx.x, lane = t & 31, w = t >> 5;
    const int wm = (w >> 2) * 64, wn = (w & 3) * 32;
    const int m0 = blockIdx.y * GBM, n0 = blockIdx.x * GBN;

    const int lrow = lane & 15;           // ldmatrix source row within 16
    const int lcol = (lane >> 4) << 3;    // ldmatrix k-col select (0 or 8)

    float acc[4][4][4];
#pragma unroll
    for (int i = 0; i < 4; i++)
#pragma unroll
        for (int j = 0; j < 4; j++)
#pragma unroll
            for (int r = 0; r < 4; r++) acc[i][j][r] = 0.f;

#define LDA(fr, mb, kb)                                                             \
    do {                                                                            \
        _Pragma("unroll")                                                           \
        for (int mi = 0; mi < 4; mi++) {                                            \
            uint32_t off = (wm + mi * 16 + lrow) * 64 + ((kb) + lcol) * 2;          \
            ldsm4(fr[mi], (mb) + SW64R(off));                                       \
        }                                                                           \
    } while (0)
#define LDB(fr, mb, kb)                                                             \
    do {                                                                            \
        _Pragma("unroll")                                                           \
        for (int bj = 0; bj < 2; bj++) {                                            \
            uint32_t r4[4];                                                         \
            uint32_t off = (wn + bj * 16 + lrow) * 64 + ((kb) + lcol) * 2;          \
            ldsm4(r4, (mb) + SW64R(off));                                           \
            fr[2 * bj + 0][0] = r4[0]; fr[2 * bj + 0][1] = r4[2];                   \
            fr[2 * bj + 1][0] = r4[1]; fr[2 * bj + 1][1] = r4[3];                   \
        }                                                                           \
    } while (0)
#define MPASS(af, bf)                                                               \
    do {                                                                            \
        _Pragma("unroll")                                                           \
        for (int mi = 0; mi < 4; mi++)                                              \
            _Pragma("unroll")                                                       \
            for (int nj = 0; nj < 4; nj++)                                          \
                mma_f16(acc[mi][nj], af[mi], bf[nj]);                               \
    } while (0)

    // prologue: chunks 0,1,2 into stages 0,1,2
    g2s_chunk(sb, A2, Wh, m0, n0, 0, t);
    asm volatile("cp.async.commit_group;" ::: "memory");
    g2s_chunk(sb + STG, A2, Wh, m0, n0, GBK, t);
    asm volatile("cp.async.commit_group;" ::: "memory");
    g2s_chunk(sb + 2 * STG, A2, Wh, m0, n0, 2 * GBK, t);
    asm volatile("cp.async.commit_group;" ::: "memory");

    int stage = 0, wstage = 3;
    for (int c = 0; c < NCH; c++) {
        if (c <= NCH - 3)      asm volatile("cp.async.wait_group 2;" ::: "memory");
        else if (c == NCH - 2) asm volatile("cp.async.wait_group 1;" ::: "memory");
        else                   asm volatile("cp.async.wait_group 0;" ::: "memory");
        __syncthreads();
        if (c + 3 < NCH) {
            g2s_chunk(sb + wstage * STG, A2, Wh, m0, n0, (c + 3) * GBK, t);
            asm volatile("cp.async.commit_group;" ::: "memory");
            wstage = (wstage + 1) & 3;
        }
        const uint32_t st = sb + stage * STG;
        stage = (stage + 1) & 3;

#pragma unroll
        for (int ks = 0; ks < 2; ks++) {
            const int kb = ks * 16;
            uint32_t ah[4][4], bh[4][2];
            LDA(ah, st, kb);
            LDB(bh, st + 2 * MATB, kb);
            MPASS(ah, bh);                    // Ah*Wh
            {
                uint32_t al[4][4];
                LDA(al, st + MATB, kb);
                MPASS(al, bh);                // Al*Wh
            }
        }
    }

    // epilogue
    const int group = lane >> 2, tig = lane & 3;
#pragma unroll
    for (int mi = 0; mi < 4; mi++)
#pragma unroll
        for (int nj = 0; nj < 4; nj++) {
            int r0 = m0 + wm + mi * 16 + group;
            int cc0 = n0 + wn + nj * 8 + tig * 2;
            float b0 = 0.f, b1 = 0.f;
            if (bias) { b0 = bias[cc0]; b1 = bias[cc0 + 1]; }
            float2 v0 = make_float2(acc[mi][nj][0] + b0, acc[mi][nj][1] + b1);
            float2 v1 = make_float2(acc[mi][nj][2] + b0, acc[mi][nj][3] + b1);
            *(float2*)(C + (size_t)r0 * Nn + cc0)       = v0;
            *(float2*)(C + (size_t)(r0 + 8) * Nn + cc0) = v1;
        }
}

// ====================== split f32 -> (hi|lo) fp16 (activations) ==================
__global__ __launch_bounds__(256) void split_kernel(
    const float* __restrict__ in, __half* __restrict__ out, int rows)
{
    size_t idx = (size_t)blockIdx.x * 256 + threadIdx.x;
    size_t row = idx >> 8;
    if (row >= (size_t)rows) return;
    int c4 = (int)(idx & 255) << 2;
    float4 v = *(const float4*)(in + row * CC + c4);
    float vv[4] = {v.x, v.y, v.z, v.w};
    __half hb[4], lb[4];
#pragma unroll
    for (int j = 0; j < 4; j++) {
        hb[j] = __float2half_rn(vv[j]);
        lb[j] = __float2half_rn(vv[j] - __half2float(hb[j]));
    }
    *(uint64_t*)(out + row * K2 + c4)      = *(uint64_t*)hb;
    *(uint64_t*)(out + row * K2 + CC + c4) = *(uint64_t*)lb;
}

// ====================== round f32 weights -> fp16 ================================
__global__ __launch_bounds__(256) void round_w_kernel(
    const float* __restrict__ in, __half* __restrict__ out, int n4)
{
    int idx = blockIdx.x * 256 + threadIdx.x;
    if (idx >= n4) return;
    float4 v = *(const float4*)(in + (size_t)idx * 4);
    __half hb[4] = {__float2half_rn(v.x), __float2half_rn(v.y),
                    __float2half_rn(v.z), __float2half_rn(v.w)};
    *(uint64_t*)(out + (size_t)idx * 4) = *(uint64_t*)hb;
}

// ================================== focus ========================================
__global__ __launch_bounds__(256) void focus_kernel(
    const float* __restrict__ scale, const float* __restrict__ pos_enc)
{
    const int row = blockIdx.x;
    const int n = row & (SEQ - 1);
    float* qp = g_qkv + (size_t)row * C3;
    float* kp = qp + CC;
    const int t = threadIdx.x;
    const int c0 = t * 4;

    float4 q4 = *(float4*)(qp + c0);
    float4 k4 = *(float4*)(kp + c0);
    const float4 pe  = *(const float4*)(pos_enc + (size_t)n * CC + c0);
    const float4 sc4 = *(const float4*)(scale + c0);

    float qv[4] = {q4.x, q4.y, q4.z, q4.w};
    float kv[4] = {k4.x + pe.x, k4.y + pe.y, k4.z + pe.z, k4.w + pe.w};
    float sv[4] = {sc4.x, sc4.y, sc4.z, sc4.w};

    float s2q = 0.f, s6q = 0.f, s2k = 0.f, s6k = 0.f;
#pragma unroll
    for (int j = 0; j < 4; j++) {
        float sc = log1pf(expf(sv[j]));
        float q = (fmaxf(qv[j], 0.f) + EPS) / sc;
        float k = (fmaxf(kv[j], 0.f) + EPS) / sc;
        qv[j] = q; kv[j] = k;
        float q2 = q * q, k2 = k * k;
        s2q += q2; s2k += k2;
        float q3 = q2 * q, k3 = k2 * k;
        s6q += q3 * q3; s6k += k3 * k3;
    }
    __shared__ float red[8][4];
    const int lid = t & 31, wid = t >> 5;
#pragma unroll
    for (int o = 16; o > 0; o >>= 1) {
        s2q += __shfl_xor_sync(0xffffffffu, s2q, o);
        s6q += __shfl_xor_sync(0xffffffffu, s6q, o);
        s2k += __shfl_xor_sync(0xffffffffu, s2k, o);
        s6k += __shfl_xor_sync(0xffffffffu, s6k, o);
    }
    if (lid == 0) { red[wid][0] = s2q; red[wid][1] = s6q; red[wid][2] = s2k; red[wid][3] = s6k; }
    __syncthreads();
    float t2q = 0.f, t6q = 0.f, t2k = 0.f, t6k = 0.f;
#pragma unroll
    for (int wq = 0; wq < 8; wq++) {
        t2q += red[wq][0]; t6q += red[wq][1]; t2k += red[wq][2]; t6k += red[wq][3];
    }
    const float fq = sqrtf(t2q / t6q);
    const float fk = sqrtf(t2k / t6k);

    float4 qo, ko;
    float* qvo = (float*)&qo; float* kvo = (float*)&ko;
#pragma unroll
    for (int j = 0; j < 4; j++) {
        qvo[j] = qv[j] * qv[j] * qv[j] * fq;
        kvo[j] = kv[j] * kv[j] * kv[j] * fk;
    }
    *(float4*)(qp + c0) = qo;
    *(float4*)(kp + c0) = ko;
}

__global__ void zero_kv_kernel()
{
    int i = blockIdx.x * 256 + threadIdx.x;
    if (i < BH * DD * DD) g_kv[i] = 0.f;
    if (i < BH * DD)      g_ksum[i] = 0.f;
}

// ==================================== kv =========================================
#define NSPLIT 8
#define NCHUNK (SEQ / NSPLIT)
__global__ __launch_bounds__(64) void kv_kernel()
{
    const int bh = blockIdx.x;
    const int sp = blockIdx.y;
    const int b = bh >> 4, h = bh & 15;
    const int n0 = sp * NCHUNK;
    __shared__ float ks[32][64];
    __shared__ float vs[32][64];
    const int t = threadIdx.x;
    const int tc = (t >> 3) << 3;
    const int td = (t & 7) << 3;
    unsigned long long acc2[8][4];
#pragma unroll
    for (int i = 0; i < 8; i++)
#pragma unroll
        for (int j = 0; j < 4; j++) acc2[i][j] = 0ULL;
    float ksacc = 0.f;

    for (int nt = 0; nt < NCHUNK; nt += 32) {
#pragma unroll
        for (int l = 0; l < 8; l++) {
            int idx4 = t + l * 64;
            int nn = idx4 >> 4, q4 = (idx4 & 15) << 2;
            size_t base = ((size_t)(b * SEQ + n0 + nt + nn)) * C3 + h * DD + q4;
            *(float4*)&ks[nn][q4] = *(const float4*)&g_qkv[base + CC];
            *(float4*)&vs[nn][q4] = *(const float4*)&g_qkv[base + 2 * CC];
        }
        __syncthreads();
#pragma unroll 4
        for (int nn = 0; nn < 32; nn++) {
            float a[8];
            *(float4*)(a)      = *(float4*)&ks[nn][tc];
            *(float4*)(a + 4)  = *(float4*)&ks[nn][tc + 4];
            unsigned long long b2[4];
            *(ulonglong2*)(b2)     = *(const ulonglong2*)(&vs[nn][td]);
            *(ulonglong2*)(b2 + 2) = *(const ulonglong2*)(&vs[nn][td + 4]);
#pragma unroll
            for (int i = 0; i < 8; i++) {
                unsigned long long a2;
                asm("mov.b64 %0, {%1, %1};" : "=l"(a2) : "f"(a[i]));
#pragma unroll
                for (int j = 0; j < 4; j++)
                    asm("fma.rn.f32x2 %0, %1, %2, %0;" : "+l"(acc2[i][j]) : "l"(a2), "l"(b2[j]));
            }
            ksacc += ks[nn][t];
        }
        __syncthreads();
    }
#pragma unroll
    for (int i = 0; i < 8; i++)
#pragma unroll
        for (int j = 0; j < 4; j++) {
            float lo, hi;
            asm("mov.b64 {%0, %1}, %2;" : "=f"(lo), "=f"(hi) : "l"(acc2[i][j]));
            atomicAdd(&g_kv[((size_t)bh * DD + tc + i) * DD + td + 2 * j], lo);
            atomicAdd(&g_kv[((size_t)bh * DD + tc + i) * DD + td + 2 * j + 1], hi);
        }
    atomicAdd(&g_ksum[bh * DD + t], ksacc);
}

// ============ o kernel: writes split fp16 (hi|lo) directly into g_o2 =============
__global__ __launch_bounds__(256) void o_kernel()
{
    const int bh = blockIdx.x;
    const int ic = blockIdx.y;
    const int b = bh >> 4, h = bh & 15;
    const int i0 = ic * 64;
    __shared__ float qs[64][68];
    __shared__ float kvs[64][64];
    __shared__ float ks_s[64];
    __shared__ float z_s[64];
    const int t = threadIdx.x;

    for (int idx = t; idx < DD * DD; idx += 256)
        kvs[idx >> 6][idx & 63] = g_kv[(size_t)bh * DD * DD + idx];
    if (t < 64) ks_s[t] = g_ksum[bh * DD + t];
    for (int idx = t; idx < 64 * 64; idx += 256) {
        int r = idx >> 6, c = idx & 63;
        qs[c][r] = g_qkv[((size_t)(b * SEQ + i0 + r)) * C3 + h * DD + c];
    }
    __syncthreads();

    if (t < 64) {
        float s = 0.f;
#pragma unroll 8
        for (int c = 0; c < 64; c++) s += qs[c][t] * ks_s[c];
        z_s[t] = 1.0f / (s + EPS);
    }
    __syncthreads();

    const int tm = (t >> 5) << 3;
    const int tn = (t & 31) << 1;
    float acc[8][2] = {};
#pragma unroll 8
    for (int c = 0; c < 64; c++) {
        float a[8];
        *(float4*)(a)     = *(float4*)&qs[c][tm];
        *(float4*)(a + 4) = *(float4*)&qs[c][tm + 4];
        float2 bv = *(float2*)&kvs[c][tn];
#pragma unroll
        for (int i = 0; i < 8; i++) {
            acc[i][0] += a[i] * bv.x;
            acc[i][1] += a[i] * bv.y;
        }
    }
#pragma unroll
    for (int i = 0; i < 8; i++) {
        float z = z_s[tm + i];
        float v0 = acc[i][0] * z, v1 = acc[i][1] * z;
        __half hb0 = __float2half_rn(v0), hb1 = __float2half_rn(v1);
        __half lb0 = __float2half_rn(v0 - __half2float(hb0));
        __half lb1 = __float2half_rn(v1 - __half2float(hb1));
        size_t off = ((size_t)(b * SEQ + i0 + tm + i)) * K2 + h * DD + tn;
        __half hp[2] = {hb0, hb1};
        __half lp[2] = {lb0, lb1};
        *(uint32_t*)(g_o2 + off)      = *(uint32_t*)hp;
        *(uint32_t*)(g_o2 + off + CC) = *(uint32_t*)lp;
    }
}

// =================================================================================
extern "C" void kernel_launch(void* const* d_in, const int* in_sizes, int n_in,
                              void* d_out, int out_size)
{
    const float* x       = (const float*)d_in[0];
    const float* scale   = (const float*)d_in[1];
    const float* pos_enc = (const float*)d_in[2];
    const float* qkv_w   = (const float*)d_in[3];
    const float* proj_w  = (const float*)d_in[4];
    const float* proj_b  = (const float*)d_in[5];
    float* out = (float*)d_out;

    float *qkv_p = nullptr;
    __half *x2_p = nullptr, *o2_p = nullptr, *wqh_p = nullptr, *wph_p = nullptr;
    cudaGetSymbolAddress((void**)&qkv_p, g_qkv);
    cudaGetSymbolAddress((void**)&x2_p, g_x2);
    cudaGetSymbolAddress((void**)&o2_p, g_o2);
    cudaGetSymbolAddress((void**)&wqh_p, g_wqh);
    cudaGetSymbolAddress((void**)&wph_p, g_wph);

    cudaFuncSetAttribute(gemm_mma, cudaFuncAttributeMaxDynamicSharedMemorySize, GSMEM);

    // 0) fp16 prep: split x (exact), round weights
    split_kernel<<<MM, 256>>>(x, x2_p, MM);
    round_w_kernel<<<(C3 * CC / 4 + 255) / 256, 256>>>(qkv_w, wqh_p, C3 * CC / 4);
    round_w_kernel<<<(CC * CC / 4 + 255) / 256, 256>>>(proj_w, wph_p, CC * CC / 4);
    // 1) qkv = x @ qkv_w^T  (HMMA fp16x2, fp32 accumulate)
    gemm_mma<<<dim3(C3 / GBN, MM / GBM), 256, GSMEM>>>(x2_p, wqh_p, nullptr, qkv_p, C3);
    // 2) focusing / activation (in-place on q,k)
    focus_kernel<<<MM, 256>>>(scale, pos_enc);
    // 3) kv = k^T v (+ ksum)
    zero_kv_kernel<<<(BH * DD * DD + 255) / 256, 256>>>();
    kv_kernel<<<dim3(BH, NSPLIT), 64>>>();
    // 4) o = z * (q @ kv), written as split fp16 in merged-head layout
    o_kernel<<<dim3(BH, SEQ / 64), 256>>>();
    // 5) out = o @ proj_w^T + proj_b  (HMMA fp16x2)
    gemm_mma<<<dim3(CC / GBN, MM / GBM), 256, GSMEM>>>(o2_p, wph_p, proj_b, out, CC);
}

// round 11
// speedup vs baseline: 2.4816x; 1.2013x over previous
#include <cuda_runtime.h>
#include <cuda_bf16.h>
#include <cuda_fp16.h>
#include <cstdint>
#include <cstddef>

// Problem constants
#define BB 8
#define SEQ 4096
#define CC 1024
#define HH 16
#define DD 64
#define MM (BB*SEQ)          // 32768
#define C3 (3*CC)            // 3072
#define BH (BB*HH)           // 128
#define EPS 1e-6f
#define K2 2048              // split activation width (hi | lo)

// ---------------- scratch (device globals; no allocation allowed) ----------------
__device__ float g_qkv[(size_t)MM * C3];          // q | k | v  (f32, focus in-place)
__device__ float g_kv[(size_t)BH * DD * DD];
__device__ float g_ksum[BH * DD];
__device__ __half g_x2[(size_t)MM * K2];          // x split   [M][hi(1024)|lo(1024)]
__device__ __half g_oh[(size_t)MM * CC];          // o (dense fp16, single-pass proj)
__device__ __half g_wqh[(size_t)C3 * CC];         // fp16(qkv_w)
__device__ __half g_wph[(size_t)CC * CC];         // fp16(proj_w)

// ================================ helpers ========================================
__device__ __forceinline__ uint32_t smem_u32(const void* p) {
    uint32_t a;
    asm("{ .reg .u64 t; cvta.to.shared.u64 t, %1; cvt.u32.u64 %0, t; }" : "=r"(a) : "l"(p));
    return a;
}
__device__ __forceinline__ void cpa16(uint32_t sa, const void* g) {
    size_t ga = __cvta_generic_to_global(g);
    asm volatile("cp.async.cg.shared.global [%0], [%1], 16;" :: "r"(sa), "l"(ga) : "memory");
}
__device__ __forceinline__ void ldsm4(uint32_t* d, uint32_t addr) {
    asm volatile("ldmatrix.sync.aligned.m8n8.x4.shared.b16 {%0,%1,%2,%3}, [%4];"
        : "=r"(d[0]), "=r"(d[1]), "=r"(d[2]), "=r"(d[3]) : "r"(addr));
}
__device__ __forceinline__ void mma_f16(float* c, const uint32_t* a, const uint32_t* b) {
    asm volatile("mma.sync.aligned.m16n8k16.row.col.f32.f16.f16.f32 "
        "{%0,%1,%2,%3}, {%4,%5,%6,%7}, {%8,%9}, {%0,%1,%2,%3};"
        : "+f"(c[0]), "+f"(c[1]), "+f"(c[2]), "+f"(c[3])
        : "r"(a[0]), "r"(a[1]), "r"(a[2]), "r"(a[3]), "r"(b[0]), "r"(b[1]));
}
// 64B-row swizzle: XOR col16 (bits[5:4]) with row bits[2:1] (off bits [8:7]).
#define SW64R(o) ((o) ^ (((o) >> 3) & 0x30))

// ============================ HMMA fp16 GEMM =====================================
// C[m,n] = sum_k A[m,k]*W[n,k];  A fp16 hi (+ optional lo plane at +CC), W fp16.
// CTAs with n0 < nskip run 2 passes (Ah*Wh + Al*Wh); others 1 pass.
// BM=128, BN=128, BK=32; 256 thr; warp 64x32; 4-stage cp.async; 2 CTAs/SM.
#define GBM 128
#define GBN 128
#define GBK 32
#define NCH (CC / GBK)          // 32 k-chunks
#define MATB (128 * 64)         // 8192 B per matrix tile (128 rows x 64B)
#define STG (3 * MATB)          // Ah|Al|Wh = 24576 B per stage
#define NSTG 4
#define GSMEM (NSTG * STG)      // 98304 B -> 2 CTAs/SM

__device__ __forceinline__ void g2s_chunk(uint32_t sbase,
    const __half* __restrict__ A2, const __half* __restrict__ Wh,
    int m0, int n0, int k0, int t, int astride, bool do_al)
{
#pragma unroll
    for (int i = 0; i < 2; i++) {
        int idx = t + i * 256;            // 512 16B-chunks per matrix
        int r = idx >> 2, j = idx & 3;
        uint32_t off = r * 64 + j * 16;
        uint32_t sw = SW64R(off);
        const __half* ga = A2 + (size_t)(m0 + r) * astride + k0 + j * 8;
        cpa16(sbase + 0 * MATB + sw, ga);
        if (do_al) cpa16(sbase + 1 * MATB + sw, ga + CC);
        const __half* gb = Wh + (size_t)(n0 + r) * CC + k0 + j * 8;
        cpa16(sbase + 2 * MATB + sw, gb);
    }
}

__global__ __launch_bounds__(256, 2) void gemm_mma(
    const __half* __restrict__ A2, const __half* __restrict__ Wh,
    const float* __restrict__ bias, float* __restrict__ C, int Nn,
    int astride, int nskip)
{
    extern __shared__ char sm[];
    const uint32_t sb = smem_u32(sm);
    const int t = threadIdx.x, lane = t & 31, w = t >> 5;
    const int wm = (w >> 2) * 64, wn = (w & 3) * 32;
    const int m0 = blockIdx.y * GBM, n0 = blockIdx.x * GBN;
    const bool do_al = n0 < nskip;

    const int lrow = lane & 15;           // ldmatrix source row within 16
    const int lcol = (lane >> 4) << 3;    // ldmatrix k-col select (0 or 8)

    float acc[4][4][4];
#pragma unroll
    for (int i = 0; i < 4; i++)
#pragma unroll
        for (int j = 0; j < 4; j++)
#pragma unroll
            for (int r = 0; r < 4; r++) acc[i][j][r] = 0.f;

#define LDA(fr, mb, kb)                                                             \
    do {                                                                            \
        _Pragma("unroll")                                                           \
        for (int mi = 0; mi < 4; mi++) {                                            \
            uint32_t off = (wm + mi * 16 + lrow) * 64 + ((kb) + lcol) * 2;          \
            ldsm4(fr[mi], (mb) + SW64R(off));                                       \
        }                                                                           \
    } while (0)
#define LDB(fr, mb, kb)                                                             \
    do {                                                                            \
        _Pragma("unroll")                                                           \
        for (int bj = 0; bj < 2; bj++) {                                            \
            uint32_t r4[4];                                                         \
            uint32_t off = (wn + bj * 16 + lrow) * 64 + ((kb) + lcol) * 2;          \
            ldsm4(r4, (mb) + SW64R(off));                                           \
            fr[2 * bj + 0][0] = r4[0]; fr[2 * bj + 0][1] = r4[2];                   \
            fr[2 * bj + 1][0] = r4[1]; fr[2 * bj + 1][1] = r4[3];                   \
        }                                                                           \
    } while (0)
#define MPASS(af, bf)                                                               \
    do {                                                                            \
        _Pragma("unroll")                                                           \
        for (int mi = 0; mi < 4; mi++)                                              \
            _Pragma("unroll")                                                       \
            for (int nj = 0; nj < 4; nj++)                                          \
                mma_f16(acc[mi][nj], af[mi], bf[nj]);                               \
    } while (0)

    // prologue: chunks 0,1,2 into stages 0,1,2
    g2s_chunk(sb, A2, Wh, m0, n0, 0, t, astride, do_al);
    asm volatile("cp.async.commit_group;" ::: "memory");
    g2s_chunk(sb + STG, A2, Wh, m0, n0, GBK, t, astride, do_al);
    asm volatile("cp.async.commit_group;" ::: "memory");
    g2s_chunk(sb + 2 * STG, A2, Wh, m0, n0, 2 * GBK, t, astride, do_al);
    asm volatile("cp.async.commit_group;" ::: "memory");

    int stage = 0, wstage = 3;
    for (int c = 0; c < NCH; c++) {
        if (c <= NCH - 3)      asm volatile("cp.async.wait_group 2;" ::: "memory");
        else if (c == NCH - 2) asm volatile("cp.async.wait_group 1;" ::: "memory");
        else                   asm volatile("cp.async.wait_group 0;" ::: "memory");
        __syncthreads();
        if (c + 3 < NCH) {
            g2s_chunk(sb + wstage * STG, A2, Wh, m0, n0, (c + 3) * GBK, t, astride, do_al);
            asm volatile("cp.async.commit_group;" ::: "memory");
            wstage = (wstage + 1) & 3;
        }
        const uint32_t st = sb + stage * STG;
        stage = (stage + 1) & 3;

#pragma unroll
        for (int ks = 0; ks < 2; ks++) {
            const int kb = ks * 16;
            uint32_t ah[4][4], bh[4][2];
            LDA(ah, st, kb);
            LDB(bh, st + 2 * MATB, kb);
            MPASS(ah, bh);                    // Ah*Wh
            if (do_al) {
                uint32_t al[4][4];
                LDA(al, st + MATB, kb);
                MPASS(al, bh);                // Al*Wh
            }
        }
    }

    // epilogue
    const int group = lane >> 2, tig = lane & 3;
#pragma unroll
    for (int mi = 0; mi < 4; mi++)
#pragma unroll
        for (int nj = 0; nj < 4; nj++) {
            int r0 = m0 + wm + mi * 16 + group;
            int cc0 = n0 + wn + nj * 8 + tig * 2;
            float b0 = 0.f, b1 = 0.f;
            if (bias) { b0 = bias[cc0]; b1 = bias[cc0 + 1]; }
            float2 v0 = make_float2(acc[mi][nj][0] + b0, acc[mi][nj][1] + b1);
            float2 v1 = make_float2(acc[mi][nj][2] + b0, acc[mi][nj][3] + b1);
            *(float2*)(C + (size_t)r0 * Nn + cc0)       = v0;
            *(float2*)(C + (size_t)(r0 + 8) * Nn + cc0) = v1;
        }
}

// ====================== split f32 -> (hi|lo) fp16 (activations) ==================
__global__ __launch_bounds__(256) void split_kernel(
    const float* __restrict__ in, __half* __restrict__ out, int rows)
{
    size_t idx = (size_t)blockIdx.x * 256 + threadIdx.x;
    size_t row = idx >> 8;
    if (row >= (size_t)rows) return;
    int c4 = (int)(idx & 255) << 2;
    float4 v = *(const float4*)(in + row * CC + c4);
    float vv[4] = {v.x, v.y, v.z, v.w};
    __half hb[4], lb[4];
#pragma unroll
    for (int j = 0; j < 4; j++) {
        hb[j] = __float2half_rn(vv[j]);
        lb[j] = __float2half_rn(vv[j] - __half2float(hb[j]));
    }
    *(uint64_t*)(out + row * K2 + c4)      = *(uint64_t*)hb;
    *(uint64_t*)(out + row * K2 + CC + c4) = *(uint64_t*)lb;
}

// ====================== round f32 weights -> fp16 ================================
__global__ __launch_bounds__(256) void round_w_kernel(
    const float* __restrict__ in, __half* __restrict__ out, int n4)
{
    int idx = blockIdx.x * 256 + threadIdx.x;
    if (idx >= n4) return;
    float4 v = *(const float4*)(in + (size_t)idx * 4);
    __half hb[4] = {__float2half_rn(v.x), __float2half_rn(v.y),
                    __float2half_rn(v.z), __float2half_rn(v.w)};
    *(uint64_t*)(out + (size_t)idx * 4) = *(uint64_t*)hb;
}

// ================================== focus ========================================
__global__ __launch_bounds__(256) void focus_kernel(
    const float* __restrict__ scale, const float* __restrict__ pos_enc)
{
    const int row = blockIdx.x;
    const int n = row & (SEQ - 1);
    float* qp = g_qkv + (size_t)row * C3;
    float* kp = qp + CC;
    const int t = threadIdx.x;
    const int c0 = t * 4;

    float4 q4 = *(float4*)(qp + c0);
    float4 k4 = *(float4*)(kp + c0);
    const float4 pe  = *(const float4*)(pos_enc + (size_t)n * CC + c0);
    const float4 sc4 = *(const float4*)(scale + c0);

    float qv[4] = {q4.x, q4.y, q4.z, q4.w};
    float kv[4] = {k4.x + pe.x, k4.y + pe.y, k4.z + pe.z, k4.w + pe.w};
    float sv[4] = {sc4.x, sc4.y, sc4.z, sc4.w};

    float s2q = 0.f, s6q = 0.f, s2k = 0.f, s6k = 0.f;
#pragma unroll
    for (int j = 0; j < 4; j++) {
        float sc = log1pf(expf(sv[j]));
        float q = (fmaxf(qv[j], 0.f) + EPS) / sc;
        float k = (fmaxf(kv[j], 0.f) + EPS) / sc;
        qv[j] = q; kv[j] = k;
        float q2 = q * q, k2 = k * k;
        s2q += q2; s2k += k2;
        float q3 = q2 * q, k3 = k2 * k;
        s6q += q3 * q3; s6k += k3 * k3;
    }
    __shared__ float red[8][4];
    const int lid = t & 31, wid = t >> 5;
#pragma unroll
    for (int o = 16; o > 0; o >>= 1) {
        s2q += __shfl_xor_sync(0xffffffffu, s2q, o);
        s6q += __shfl_xor_sync(0xffffffffu, s6q, o);
        s2k += __shfl_xor_sync(0xffffffffu, s2k, o);
        s6k += __shfl_xor_sync(0xffffffffu, s6k, o);
    }
    if (lid == 0) { red[wid][0] = s2q; red[wid][1] = s6q; red[wid][2] = s2k; red[wid][3] = s6k; }
    __syncthreads();
    float t2q = 0.f, t6q = 0.f, t2k = 0.f, t6k = 0.f;
#pragma unroll
    for (int wq = 0; wq < 8; wq++) {
        t2q += red[wq][0]; t6q += red[wq][1]; t2k += red[wq][2]; t6k += red[wq][3];
    }
    const float fq = sqrtf(t2q / t6q);
    const float fk = sqrtf(t2k / t6k);

    float4 qo, ko;
    float* qvo = (float*)&qo; float* kvo = (float*)&ko;
#pragma unroll
    for (int j = 0; j < 4; j++) {
        qvo[j] = qv[j] * qv[j] * qv[j] * fq;
        kvo[j] = kv[j] * kv[j] * kv[j] * fk;
    }
    *(float4*)(qp + c0) = qo;
    *(float4*)(kp + c0) = ko;
}

__global__ void zero_kv_kernel()
{
    int i = blockIdx.x * 256 + threadIdx.x;
    if (i < BH * DD * DD) g_kv[i] = 0.f;
    if (i < BH * DD)      g_ksum[i] = 0.f;
}

// ==================================== kv =========================================
#define NSPLIT 8
#define NCHUNK (SEQ / NSPLIT)
__global__ __launch_bounds__(64) void kv_kernel()
{
    const int bh = blockIdx.x;
    const int sp = blockIdx.y;
    const int b = bh >> 4, h = bh & 15;
    const int n0 = sp * NCHUNK;
    __shared__ float ks[32][64];
    __shared__ float vs[32][64];
    const int t = threadIdx.x;
    const int tc = (t >> 3) << 3;
    const int td = (t & 7) << 3;
    unsigned long long acc2[8][4];
#pragma unroll
    for (int i = 0; i < 8; i++)
#pragma unroll
        for (int j = 0; j < 4; j++) acc2[i][j] = 0ULL;
    float ksacc = 0.f;

    for (int nt = 0; nt < NCHUNK; nt += 32) {
#pragma unroll
        for (int l = 0; l < 8; l++) {
            int idx4 = t + l * 64;
            int nn = idx4 >> 4, q4 = (idx4 & 15) << 2;
            size_t base = ((size_t)(b * SEQ + n0 + nt + nn)) * C3 + h * DD + q4;
            *(float4*)&ks[nn][q4] = *(const float4*)&g_qkv[base + CC];
            *(float4*)&vs[nn][q4] = *(const float4*)&g_qkv[base + 2 * CC];
        }
        __syncthreads();
#pragma unroll 4
        for (int nn = 0; nn < 32; nn++) {
            float a[8];
            *(float4*)(a)      = *(float4*)&ks[nn][tc];
            *(float4*)(a + 4)  = *(float4*)&ks[nn][tc + 4];
            unsigned long long b2[4];
            *(ulonglong2*)(b2)     = *(const ulonglong2*)(&vs[nn][td]);
            *(ulonglong2*)(b2 + 2) = *(const ulonglong2*)(&vs[nn][td + 4]);
#pragma unroll
            for (int i = 0; i < 8; i++) {
                unsigned long long a2;
                asm("mov.b64 %0, {%1, %1};" : "=l"(a2) : "f"(a[i]));
#pragma unroll
                for (int j = 0; j < 4; j++)
                    asm("fma.rn.f32x2 %0, %1, %2, %0;" : "+l"(acc2[i][j]) : "l"(a2), "l"(b2[j]));
            }
            ksacc += ks[nn][t];
        }
        __syncthreads();
    }
#pragma unroll
    for (int i = 0; i < 8; i++)
#pragma unroll
        for (int j = 0; j < 4; j++) {
            float lo, hi;
            asm("mov.b64 {%0, %1}, %2;" : "=f"(lo), "=f"(hi) : "l"(acc2[i][j]));
            atomicAdd(&g_kv[((size_t)bh * DD + tc + i) * DD + td + 2 * j], lo);
            atomicAdd(&g_kv[((size_t)bh * DD + tc + i) * DD + td + 2 * j + 1], hi);
        }
    atomicAdd(&g_ksum[bh * DD + t], ksacc);
}

// ============ o kernel: writes dense fp16 o directly into g_oh ===================
__global__ __launch_bounds__(256) void o_kernel()
{
    const int bh = blockIdx.x;
    const int ic = blockIdx.y;
    const int b = bh >> 4, h = bh & 15;
    const int i0 = ic * 64;
    __shared__ float qs[64][68];
    __shared__ float kvs[64][64];
    __shared__ float ks_s[64];
    __shared__ float z_s[64];
    const int t = threadIdx.x;

    for (int idx = t; idx < DD * DD; idx += 256)
        kvs[idx >> 6][idx & 63] = g_kv[(size_t)bh * DD * DD + idx];
    if (t < 64) ks_s[t] = g_ksum[bh * DD + t];
    for (int idx = t; idx < 64 * 64; idx += 256) {
        int r = idx >> 6, c = idx & 63;
        qs[c][r] = g_qkv[((size_t)(b * SEQ + i0 + r)) * C3 + h * DD + c];
    }
    __syncthreads();

    if (t < 64) {
        float s = 0.f;
#pragma unroll 8
        for (int c = 0; c < 64; c++) s += qs[c][t] * ks_s[c];
        z_s[t] = 1.0f / (s + EPS);
    }
    __syncthreads();

    const int tm = (t >> 5) << 3;
    const int tn = (t & 31) << 1;
    float acc[8][2] = {};
#pragma unroll 8
    for (int c = 0; c < 64; c++) {
        float a[8];
        *(float4*)(a)     = *(float4*)&qs[c][tm];
        *(float4*)(a + 4) = *(float4*)&qs[c][tm + 4];
        float2 bv = *(float2*)&kvs[c][tn];
#pragma unroll
        for (int i = 0; i < 8; i++) {
            acc[i][0] += a[i] * bv.x;
            acc[i][1] += a[i] * bv.y;
        }
    }
#pragma unroll
    for (int i = 0; i < 8; i++) {
        float z = z_s[tm + i];
        __half hp[2] = {__float2half_rn(acc[i][0] * z), __float2half_rn(acc[i][1] * z)};
        size_t off = ((size_t)(b * SEQ + i0 + tm + i)) * CC + h * DD + tn;
        *(uint32_t*)(g_oh + off) = *(uint32_t*)hp;
    }
}

// =================================================================================
extern "C" void kernel_launch(void* const* d_in, const int* in_sizes, int n_in,
                              void* d_out, int out_size)
{
    const float* x       = (const float*)d_in[0];
    const float* scale   = (const float*)d_in[1];
    const float* pos_enc = (const float*)d_in[2];
    const float* qkv_w   = (const float*)d_in[3];
    const float* proj_w  = (const float*)d_in[4];
    const float* proj_b  = (const float*)d_in[5];
    float* out = (float*)d_out;

    float *qkv_p = nullptr;
    __half *x2_p = nullptr, *oh_p = nullptr, *wqh_p = nullptr, *wph_p = nullptr;
    cudaGetSymbolAddress((void**)&qkv_p, g_qkv);
    cudaGetSymbolAddress((void**)&x2_p, g_x2);
    cudaGetSymbolAddress((void**)&oh_p, g_oh);
    cudaGetSymbolAddress((void**)&wqh_p, g_wqh);
    cudaGetSymbolAddress((void**)&wph_p, g_wph);

    cudaFuncSetAttribute(gemm_mma, cudaFuncAttributeMaxDynamicSharedMemorySize, GSMEM);

    // 0) fp16 prep: split x (exact), round weights
    split_kernel<<<MM, 256>>>(x, x2_p, MM);
    round_w_kernel<<<(C3 * CC / 4 + 255) / 256, 256>>>(qkv_w, wqh_p, C3 * CC / 4);
    round_w_kernel<<<(CC * CC / 4 + 255) / 256, 256>>>(proj_w, wph_p, CC * CC / 4);
    // 1) qkv = x @ qkv_w^T  (2-pass for q,k columns; 1-pass for v columns)
    gemm_mma<<<dim3(C3 / GBN, MM / GBM), 256, GSMEM>>>(x2_p, wqh_p, nullptr, qkv_p, C3, K2, 2048);
    // 2) focusing / activation (in-place on q,k)
    focus_kernel<<<MM, 256>>>(scale, pos_enc);
    // 3) kv = k^T v (+ ksum)
    zero_kv_kernel<<<(BH * DD * DD + 255) / 256, 256>>>();
    kv_kernel<<<dim3(BH, NSPLIT), 64>>>();
    // 4) o = z * (q @ kv), dense fp16 merged-head layout
    o_kernel<<<dim3(BH, SEQ / 64), 256>>>();
    // 5) out = o @ proj_w^T + proj_b  (single-pass fp16)
    gemm_mma<<<dim3(CC / GBN, MM / GBM), 256, GSMEM>>>(oh_p, wph_p, proj_b, out, CC, CC, 0);
}

// round 12
// speedup vs baseline: 2.6307x; 1.0601x over previous
#include <cuda_runtime.h>
#include <cuda_bf16.h>
#include <cuda_fp16.h>
#include <cstdint>
#include <cstddef>

// Problem constants
#define BB 8
#define SEQ 4096
#define CC 1024
#define HH 16
#define DD 64
#define MM (BB*SEQ)          // 32768
#define C3 (3*CC)            // 3072
#define BH (BB*HH)           // 128
#define EPS 1e-6f
#define K2 2048              // split weight width (hi | lo)

// ---------------- scratch (device globals; no allocation allowed) ----------------
__device__ float g_qkv[(size_t)MM * C3];          // q | k | v  (f32, focus in-place)
__device__ float g_kv[(size_t)BH * DD * DD];
__device__ float g_ksum[BH * DD];
__device__ __half g_xh[(size_t)MM * CC];          // fp16(x), dense
__device__ __half g_oh[(size_t)MM * CC];          // o (dense fp16)
__device__ __half g_wq2[(size_t)C3 * K2];         // qkv_w split [row][hi(1024)|lo(1024)]
__device__ __half g_wph[(size_t)CC * CC];         // fp16(proj_w), dense

// ================================ helpers ========================================
__device__ __forceinline__ uint32_t smem_u32(const void* p) {
    uint32_t a;
    asm("{ .reg .u64 t; cvta.to.shared.u64 t, %1; cvt.u32.u64 %0, t; }" : "=r"(a) : "l"(p));
    return a;
}
__device__ __forceinline__ void cpa16(uint32_t sa, const void* g) {
    size_t ga = __cvta_generic_to_global(g);
    asm volatile("cp.async.cg.shared.global [%0], [%1], 16;" :: "r"(sa), "l"(ga) : "memory");
}
__device__ __forceinline__ void ldsm4(uint32_t* d, uint32_t addr) {
    asm volatile("ldmatrix.sync.aligned.m8n8.x4.shared.b16 {%0,%1,%2,%3}, [%4];"
        : "=r"(d[0]), "=r"(d[1]), "=r"(d[2]), "=r"(d[3]) : "r"(addr));
}
__device__ __forceinline__ void mma_f16(float* c, const uint32_t* a, const uint32_t* b) {
    asm volatile("mma.sync.aligned.m16n8k16.row.col.f32.f16.f16.f32 "
        "{%0,%1,%2,%3}, {%4,%5,%6,%7}, {%8,%9}, {%0,%1,%2,%3};"
        : "+f"(c[0]), "+f"(c[1]), "+f"(c[2]), "+f"(c[3])
        : "r"(a[0]), "r"(a[1]), "r"(a[2]), "r"(a[3]), "r"(b[0]), "r"(b[1]));
}
// 64B-row swizzle: XOR col16 (bits[5:4]) with row bits[2:1] (off bits [8:7]).
#define SW64R(o) ((o) ^ (((o) >> 3) & 0x30))

// ============================ HMMA fp16 GEMM =====================================
// C[m,n] = sum_k A[m,k]*W[n,k];  A dense fp16, W fp16 hi (+ optional lo at +CC).
// CTAs with n0 < nskip run 2 passes (A*Wh + A*Wl); others 1 pass.
// A-fragments loaded ONCE per ks and reused across both passes (smem-port relief).
// BM=128, BN=128, BK=32; 256 thr; warp 64x32; 4-stage cp.async; 2 CTAs/SM.
#define GBM 128
#define GBN 128
#define GBK 32
#define NCH (CC / GBK)          // 32 k-chunks
#define MATB (128 * 64)         // 8192 B per matrix tile (128 rows x 64B)
#define STG (3 * MATB)          // A|Wh|Wl = 24576 B per stage
#define NSTG 4
#define GSMEM (NSTG * STG)      // 98304 B -> 2 CTAs/SM

__device__ __forceinline__ void g2s_chunk(uint32_t sbase,
    const __half* __restrict__ A, const __half* __restrict__ W2,
    int m0, int n0, int k0, int t, int wstride, bool do_wl)
{
#pragma unroll
    for (int i = 0; i < 2; i++) {
        int idx = t + i * 256;            // 512 16B-chunks per matrix
        int r = idx >> 2, j = idx & 3;
        uint32_t off = r * 64 + j * 16;
        uint32_t sw = SW64R(off);
        const __half* ga = A + (size_t)(m0 + r) * CC + k0 + j * 8;
        cpa16(sbase + 0 * MATB + sw, ga);
        const __half* gb = W2 + (size_t)(n0 + r) * wstride + k0 + j * 8;
        cpa16(sbase + 1 * MATB + sw, gb);
        if (do_wl) cpa16(sbase + 2 * MATB + sw, gb + CC);
    }
}

__global__ __launch_bounds__(256, 2) void gemm_mma(
    const __half* __restrict__ A, const __half* __restrict__ W2,
    const float* __restrict__ bias, float* __restrict__ C, int Nn,
    int wstride, int nskip)
{
    extern __shared__ char sm[];
    const uint32_t sb = smem_u32(sm);
    const int t = threadIdx.x, lane = t & 31, w = t >> 5;
    const int wm = (w >> 2) * 64, wn = (w & 3) * 32;
    const int m0 = blockIdx.y * GBM, n0 = blockIdx.x * GBN;
    const bool do_wl = n0 < nskip;

    const int lrow = lane & 15;           // ldmatrix source row within 16
    const int lcol = (lane >> 4) << 3;    // ldmatrix k-col select (0 or 8)

    float acc[4][4][4];
#pragma unroll
    for (int i = 0; i < 4; i++)
#pragma unroll
        for (int j = 0; j < 4; j++)
#pragma unroll
            for (int r = 0; r < 4; r++) acc[i][j][r] = 0.f;

#define LDA(fr, mb, kb)                                                             \
    do {                                                                            \
        _Pragma("unroll")                                                           \
        for (int mi = 0; mi < 4; mi++) {                                            \
            uint32_t off = (wm + mi * 16 + lrow) * 64 + ((kb) + lcol) * 2;          \
            ldsm4(fr[mi], (mb) + SW64R(off));                                       \
        }                                                                           \
    } while (0)
#define LDB(fr, mb, kb)                                                             \
    do {                                                                            \
        _Pragma("unroll")                                                           \
        for (int bj = 0; bj < 2; bj++) {                                            \
            uint32_t r4[4];                                                         \
            uint32_t off = (wn + bj * 16 + lrow) * 64 + ((kb) + lcol) * 2;          \
            ldsm4(r4, (mb) + SW64R(off));                                           \
            fr[2 * bj + 0][0] = r4[0]; fr[2 * bj + 0][1] = r4[2];                   \
            fr[2 * bj + 1][0] = r4[1]; fr[2 * bj + 1][1] = r4[3];                   \
        }                                                                           \
    } while (0)
#define MPASS(af, bf)                                                               \
    do {                                                                            \
        _Pragma("unroll")                                                           \
        for (int mi = 0; mi < 4; mi++)                                              \
            _Pragma("unroll")                                                       \
            for (int nj = 0; nj < 4; nj++)                                          \
                mma_f16(acc[mi][nj], af[mi], bf[nj]);                               \
    } while (0)

    // prologue: chunks 0,1,2 into stages 0,1,2
    g2s_chunk(sb, A, W2, m0, n0, 0, t, wstride, do_wl);
    asm volatile("cp.async.commit_group;" ::: "memory");
    g2s_chunk(sb + STG, A, W2, m0, n0, GBK, t, wstride, do_wl);
    asm volatile("cp.async.commit_group;" ::: "memory");
    g2s_chunk(sb + 2 * STG, A, W2, m0, n0, 2 * GBK, t, wstride, do_wl);
    asm volatile("cp.async.commit_group;" ::: "memory");

    int stage = 0, wstage = 3;
    for (int c = 0; c < NCH; c++) {
        if (c <= NCH - 3)      asm volatile("cp.async.wait_group 2;" ::: "memory");
        else if (c == NCH - 2) asm volatile("cp.async.wait_group 1;" ::: "memory");
        else                   asm volatile("cp.async.wait_group 0;" ::: "memory");
        __syncthreads();
        if (c + 3 < NCH) {
            g2s_chunk(sb + wstage * STG, A, W2, m0, n0, (c + 3) * GBK, t, wstride, do_wl);
            asm volatile("cp.async.commit_group;" ::: "memory");
            wstage = (wstage + 1) & 3;
        }
        const uint32_t st = sb + stage * STG;
        stage = (stage + 1) & 3;

#pragma unroll
        for (int ks = 0; ks < 2; ks++) {
            const int kb = ks * 16;
            uint32_t ah[4][4], bh[4][2];
            LDA(ah, st, kb);                      // A loaded ONCE per ks
            LDB(bh, st + 1 * MATB, kb);
            MPASS(ah, bh);                        // A*Wh
            if (do_wl) {
                uint32_t bl[4][2];
                LDB(bl, st + 2 * MATB, kb);
                MPASS(ah, bl);                    // A*Wl (A frags reused)
            }
        }
    }

    // epilogue
    const int group = lane >> 2, tig = lane & 3;
#pragma unroll
    for (int mi = 0; mi < 4; mi++)
#pragma unroll
        for (int nj = 0; nj < 4; nj++) {
            int r0 = m0 + wm + mi * 16 + group;
            int cc0 = n0 + wn + nj * 8 + tig * 2;
            float b0 = 0.f, b1 = 0.f;
            if (bias) { b0 = bias[cc0]; b1 = bias[cc0 + 1]; }
            float2 v0 = make_float2(acc[mi][nj][0] + b0, acc[mi][nj][1] + b1);
            float2 v1 = make_float2(acc[mi][nj][2] + b0, acc[mi][nj][3] + b1);
            *(float2*)(C + (size_t)r0 * Nn + cc0)       = v0;
            *(float2*)(C + (size_t)(r0 + 8) * Nn + cc0) = v1;
        }
}

// ====================== split f32 -> (hi|lo) fp16 (weights) ======================
__global__ __launch_bounds__(256) void split_kernel(
    const float* __restrict__ in, __half* __restrict__ out, int rows)
{
    size_t idx = (size_t)blockIdx.x * 256 + threadIdx.x;
    size_t row = idx >> 8;
    if (row >= (size_t)rows) return;
    int c4 = (int)(idx & 255) << 2;
    float4 v = *(const float4*)(in + row * CC + c4);
    float vv[4] = {v.x, v.y, v.z, v.w};
    __half hb[4], lb[4];
#pragma unroll
    for (int j = 0; j < 4; j++) {
        hb[j] = __float2half_rn(vv[j]);
        lb[j] = __float2half_rn(vv[j] - __half2float(hb[j]));
    }
    *(uint64_t*)(out + row * K2 + c4)      = *(uint64_t*)hb;
    *(uint64_t*)(out + row * K2 + CC + c4) = *(uint64_t*)lb;
}

// ====================== round f32 -> dense fp16 ==================================
__global__ __launch_bounds__(256) void round_kernel(
    const float* __restrict__ in, __half* __restrict__ out, int n4)
{
    int idx = blockIdx.x * 256 + threadIdx.x;
    if (idx >= n4) return;
    float4 v = *(const float4*)(in + (size_t)idx * 4);
    __half hb[4] = {__float2half_rn(v.x), __float2half_rn(v.y),
                    __float2half_rn(v.z), __float2half_rn(v.w)};
    *(uint64_t*)(out + (size_t)idx * 4) = *(uint64_t*)hb;
}

// ================================== focus ========================================
__global__ __launch_bounds__(256) void focus_kernel(
    const float* __restrict__ scale, const float* __restrict__ pos_enc)
{
    const int row = blockIdx.x;
    const int n = row & (SEQ - 1);
    float* qp = g_qkv + (size_t)row * C3;
    float* kp = qp + CC;
    const int t = threadIdx.x;
    const int c0 = t * 4;

    float4 q4 = *(float4*)(qp + c0);
    float4 k4 = *(float4*)(kp + c0);
    const float4 pe  = *(const float4*)(pos_enc + (size_t)n * CC + c0);
    const float4 sc4 = *(const float4*)(scale + c0);

    float qv[4] = {q4.x, q4.y, q4.z, q4.w};
    float kv[4] = {k4.x + pe.x, k4.y + pe.y, k4.z + pe.z, k4.w + pe.w};
    float sv[4] = {sc4.x, sc4.y, sc4.z, sc4.w};

    float s2q = 0.f, s6q = 0.f, s2k = 0.f, s6k = 0.f;
#pragma unroll
    for (int j = 0; j < 4; j++) {
        float sc = log1pf(expf(sv[j]));
        float q = (fmaxf(qv[j], 0.f) + EPS) / sc;
        float k = (fmaxf(kv[j], 0.f) + EPS) / sc;
        qv[j] = q; kv[j] = k;
        float q2 = q * q, k2 = k * k;
        s2q += q2; s2k += k2;
        float q3 = q2 * q, k3 = k2 * k;
        s6q += q3 * q3; s6k += k3 * k3;
    }
    __shared__ float red[8][4];
    const int lid = t & 31, wid = t >> 5;
#pragma unroll
    for (int o = 16; o > 0; o >>= 1) {
        s2q += __shfl_xor_sync(0xffffffffu, s2q, o);
        s6q += __shfl_xor_sync(0xffffffffu, s6q, o);
        s2k += __shfl_xor_sync(0xffffffffu, s2k, o);
        s6k += __shfl_xor_sync(0xffffffffu, s6k, o);
    }
    if (lid == 0) { red[wid][0] = s2q; red[wid][1] = s6q; red[wid][2] = s2k; red[wid][3] = s6k; }
    __syncthreads();
    float t2q = 0.f, t6q = 0.f, t2k = 0.f, t6k = 0.f;
#pragma unroll
    for (int wq = 0; wq < 8; wq++) {
        t2q += red[wq][0]; t6q += red[wq][1]; t2k += red[wq][2]; t6k += red[wq][3];
    }
    const float fq = sqrtf(t2q / t6q);
    const float fk = sqrtf(t2k / t6k);

    float4 qo, ko;
    float* qvo = (float*)&qo; float* kvo = (float*)&ko;
#pragma unroll
    for (int j = 0; j < 4; j++) {
        qvo[j] = qv[j] * qv[j] * qv[j] * fq;
        kvo[j] = kv[j] * kv[j] * kv[j] * fk;
    }
    *(float4*)(qp + c0) = qo;
    *(float4*)(kp + c0) = ko;
}

__global__ void zero_kv_kernel()
{
    int i = blockIdx.x * 256 + threadIdx.x;
    if (i < BH * DD * DD) g_kv[i] = 0.f;
    if (i < BH * DD)      g_ksum[i] = 0.f;
}

// ==================================== kv =========================================
#define NSPLIT 8
#define NCHUNK (SEQ / NSPLIT)
__global__ __launch_bounds__(64) void kv_kernel()
{
    const int bh = blockIdx.x;
    const int sp = blockIdx.y;
    const int b = bh >> 4, h = bh & 15;
    const int n0 = sp * NCHUNK;
    __shared__ float ks[32][64];
    __shared__ float vs[32][64];
    const int t = threadIdx.x;
    const int tc = (t >> 3) << 3;
    const int td = (t & 7) << 3;
    unsigned long long acc2[8][4];
#pragma unroll
    for (int i = 0; i < 8; i++)
#pragma unroll
        for (int j = 0; j < 4; j++) acc2[i][j] = 0ULL;
    float ksacc = 0.f;

    for (int nt = 0; nt < NCHUNK; nt += 32) {
#pragma unroll
        for (int l = 0; l < 8; l++) {
            int idx4 = t + l * 64;
            int nn = idx4 >> 4, q4 = (idx4 & 15) << 2;
            size_t base = ((size_t)(b * SEQ + n0 + nt + nn)) * C3 + h * DD + q4;
            *(float4*)&ks[nn][q4] = *(const float4*)&g_qkv[base + CC];
            *(float4*)&vs[nn][q4] = *(const float4*)&g_qkv[base + 2 * CC];
        }
        __syncthreads();
#pragma unroll 4
        for (int nn = 0; nn < 32; nn++) {
            float a[8];
            *(float4*)(a)      = *(float4*)&ks[nn][tc];
            *(float4*)(a + 4)  = *(float4*)&ks[nn][tc + 4];
            unsigned long long b2[4];
            *(ulonglong2*)(b2)     = *(const ulonglong2*)(&vs[nn][td]);
            *(ulonglong2*)(b2 + 2) = *(const ulonglong2*)(&vs[nn][td + 4]);
#pragma unroll
            for (int i = 0; i < 8; i++) {
                unsigned long long a2;
                asm("mov.b64 %0, {%1, %1};" : "=l"(a2) : "f"(a[i]));
#pragma unroll
                for (int j = 0; j < 4; j++)
                    asm("fma.rn.f32x2 %0, %1, %2, %0;" : "+l"(acc2[i][j]) : "l"(a2), "l"(b2[j]));
            }
            ksacc += ks[nn][t];
        }
        __syncthreads();
    }
#pragma unroll
    for (int i = 0; i < 8; i++)
#pragma unroll
        for (int j = 0; j < 4; j++) {
            float lo, hi;
            asm("mov.b64 {%0, %1}, %2;" : "=f"(lo), "=f"(hi) : "l"(acc2[i][j]));
            atomicAdd(&g_kv[((size_t)bh * DD + tc + i) * DD + td + 2 * j], lo);
            atomicAdd(&g_kv[((size_t)bh * DD + tc + i) * DD + td + 2 * j + 1], hi);
        }
    atomicAdd(&g_ksum[bh * DD + t], ksacc);
}

// ============ o kernel: writes dense fp16 o directly into g_oh ===================
__global__ __launch_bounds__(256) void o_kernel()
{
    const int bh = blockIdx.x;
    const int ic = blockIdx.y;
    const int b = bh >> 4, h = bh & 15;
    const int i0 = ic * 64;
    __shared__ float qs[64][68];
    __shared__ float kvs[64][64];
    __shared__ float ks_s[64];
    __shared__ float z_s[64];
    const int t = threadIdx.x;

    for (int idx = t; idx < DD * DD; idx += 256)
        kvs[idx >> 6][idx & 63] = g_kv[(size_t)bh * DD * DD + idx];
    if (t < 64) ks_s[t] = g_ksum[bh * DD + t];
    for (int idx = t; idx < 64 * 64; idx += 256) {
        int r = idx >> 6, c = idx & 63;
        qs[c][r] = g_qkv[((size_t)(b * SEQ + i0 + r)) * C3 + h * DD + c];
    }
    __syncthreads();

    if (t < 64) {
        float s = 0.f;
#pragma unroll 8
        for (int c = 0; c < 64; c++) s += qs[c][t] * ks_s[c];
        z_s[t] = 1.0f / (s + EPS);
    }
    __syncthreads();

    const int tm = (t >> 5) << 3;
    const int tn = (t & 31) << 1;
    float acc[8][2] = {};
#pragma unroll 8
    for (int c = 0; c < 64; c++) {
        float a[8];
        *(float4*)(a)     = *(float4*)&qs[c][tm];
        *(float4*)(a + 4) = *(float4*)&qs[c][tm + 4];
        float2 bv = *(float2*)&kvs[c][tn];
#pragma unroll
        for (int i = 0; i < 8; i++) {
            acc[i][0] += a[i] * bv.x;
            acc[i][1] += a[i] * bv.y;
        }
    }
#pragma unroll
    for (int i = 0; i < 8; i++) {
        float z = z_s[tm + i];
        __half hp[2] = {__float2half_rn(acc[i][0] * z), __float2half_rn(acc[i][1] * z)};
        size_t off = ((size_t)(b * SEQ + i0 + tm + i)) * CC + h * DD + tn;
        *(uint32_t*)(g_oh + off) = *(uint32_t*)hp;
    }
}

// =================================================================================
extern "C" void kernel_launch(void* const* d_in, const int* in_sizes, int n_in,
                              void* d_out, int out_size)
{
    const float* x       = (const float*)d_in[0];
    const float* scale   = (const float*)d_in[1];
    const float* pos_enc = (const float*)d_in[2];
    const float* qkv_w   = (const float*)d_in[3];
    const float* proj_w  = (const float*)d_in[4];
    const float* proj_b  = (const float*)d_in[5];
    float* out = (float*)d_out;

    float *qkv_p = nullptr;
    __half *xh_p = nullptr, *oh_p = nullptr, *wq2_p = nullptr, *wph_p = nullptr;
    cudaGetSymbolAddress((void**)&qkv_p, g_qkv);
    cudaGetSymbolAddress((void**)&xh_p, g_xh);
    cudaGetSymbolAddress((void**)&oh_p, g_oh);
    cudaGetSymbolAddress((void**)&wq2_p, g_wq2);
    cudaGetSymbolAddress((void**)&wph_p, g_wph);

    cudaFuncSetAttribute(gemm_mma, cudaFuncAttributeMaxDynamicSharedMemorySize, GSMEM);

    // 0) fp16 prep: round x dense; split qkv_w (hi|lo); round proj_w dense
    round_kernel<<<(MM * CC / 4 + 255) / 256, 256>>>(x, xh_p, MM * CC / 4);
    split_kernel<<<C3, 256>>>(qkv_w, wq2_p, C3);
    round_kernel<<<(CC * CC / 4 + 255) / 256, 256>>>(proj_w, wph_p, CC * CC / 4);
    // 1) qkv = xh @ (Wh+Wl)^T  (2-pass for q,k columns; 1-pass for v columns)
    gemm_mma<<<dim3(C3 / GBN, MM / GBM), 256, GSMEM>>>(xh_p, wq2_p, nullptr, qkv_p, C3, K2, 2048);
    // 2) focusing / activation (in-place on q,k)
    focus_kernel<<<MM, 256>>>(scale, pos_enc);
    // 3) kv = k^T v (+ ksum)
    zero_kv_kernel<<<(BH * DD * DD + 255) / 256, 256>>>();
    kv_kernel<<<dim3(BH, NSPLIT), 64>>>();
    // 4) o = z * (q @ kv), dense fp16 merged-head layout
    o_kernel<<<dim3(BH, SEQ / 64), 256>>>();
    // 5) out = o @ proj_w^T + proj_b  (single-pass fp16)
    gemm_mma<<<dim3(CC / GBN, MM / GBM), 256, GSMEM>>>(oh_p, wph_p, proj_b, out, CC, CC, 0);
}

// round 13
// speedup vs baseline: 2.9927x; 1.1376x over previous
#include <cuda_runtime.h>
#include <cuda_bf16.h>
#include <cuda_fp16.h>
#include <cstdint>
#include <cstddef>

// Problem constants
#define BB 8
#define SEQ 4096
#define CC 1024
#define HH 16
#define DD 64
#define MM (BB*SEQ)          // 32768
#define C3 (3*CC)            // 3072
#define BH (BB*HH)           // 128
#define EPS 1e-6f
#define K2 2048              // split weight width (hi | lo)

// ---------------- scratch (device globals; no allocation allowed) ----------------
__device__ float g_qkv[(size_t)MM * 2048];        // q | k  (f32, ldc 2048)
__device__ float g_kv[(size_t)BH * DD * DD];
__device__ float g_ksum[BH * DD];
__device__ __half g_xh[(size_t)MM * CC];          // fp16(x)
__device__ __half g_qh[(size_t)MM * CC];          // fp16 q (post-focus)
__device__ __half g_kh[(size_t)MM * CC];          // fp16 k (post-focus)
__device__ __half g_vh[(size_t)MM * CC];          // fp16 v (from qkv epilogue)
__device__ __half g_oh[(size_t)MM * CC];          // fp16 o
__device__ __half g_kvt[(size_t)BH * DD * DD];    // fp16 kv^T [bh][d][c]
__device__ __half g_wq2[(size_t)C3 * K2];         // qkv_w split [row][hi|lo]
__device__ __half g_wph[(size_t)CC * CC];         // fp16(proj_w)

// ================================ helpers ========================================
__device__ __forceinline__ uint32_t smem_u32(const void* p) {
    uint32_t a;
    asm("{ .reg .u64 t; cvta.to.shared.u64 t, %1; cvt.u32.u64 %0, t; }" : "=r"(a) : "l"(p));
    return a;
}
__device__ __forceinline__ void cpa16(uint32_t sa, const void* g) {
    size_t ga = __cvta_generic_to_global(g);
    asm volatile("cp.async.cg.shared.global [%0], [%1], 16;" :: "r"(sa), "l"(ga) : "memory");
}
__device__ __forceinline__ void ldsm4(uint32_t* d, uint32_t addr) {
    asm volatile("ldmatrix.sync.aligned.m8n8.x4.shared.b16 {%0,%1,%2,%3}, [%4];"
        : "=r"(d[0]), "=r"(d[1]), "=r"(d[2]), "=r"(d[3]) : "r"(addr));
}
__device__ __forceinline__ void ldsm4t(uint32_t* d, uint32_t addr) {
    asm volatile("ldmatrix.sync.aligned.m8n8.x4.trans.shared.b16 {%0,%1,%2,%3}, [%4];"
        : "=r"(d[0]), "=r"(d[1]), "=r"(d[2]), "=r"(d[3]) : "r"(addr));
}
__device__ __forceinline__ void mma_f16(float* c, const uint32_t* a, const uint32_t* b) {
    asm volatile("mma.sync.aligned.m16n8k16.row.col.f32.f16.f16.f32 "
        "{%0,%1,%2,%3}, {%4,%5,%6,%7}, {%8,%9}, {%0,%1,%2,%3};"
        : "+f"(c[0]), "+f"(c[1]), "+f"(c[2]), "+f"(c[3])
        : "r"(a[0]), "r"(a[1]), "r"(a[2]), "r"(a[3]), "r"(b[0]), "r"(b[1]));
}
#define SW64R(o) ((o) ^ (((o) >> 3) & 0x30))
#define SW128(o) ((o) ^ (((o) >> 3) & 0x70))

// ============================ HMMA fp16 GEMM =====================================
// C[m,n] = sum_k A[m,k]*W[n,k];  A dense fp16, W fp16 hi (+ optional lo at +CC).
// n0 < nskip: 2 passes (A*Wh + A*Wl); else 1 pass. A frags reused across passes.
// Optional fp16 output region: columns >= vcol0 go to vout (stride CC) as fp16.
#define GBM 128
#define GBN 128
#define GBK 32
#define NCH (CC / GBK)          // 32 k-chunks
#define MATB (128 * 64)         // 8192 B per matrix tile (128 rows x 64B)
#define STG (3 * MATB)          // A|Wh|Wl = 24576 B per stage
#define NSTG 4
#define GSMEM (NSTG * STG)      // 98304 B -> 2 CTAs/SM

__device__ __forceinline__ void g2s_chunk(uint32_t sbase,
    const __half* __restrict__ A, const __half* __restrict__ W2,
    int m0, int n0, int k0, int t, int wstride, bool do_wl)
{
#pragma unroll
    for (int i = 0; i < 2; i++) {
        int idx = t + i * 256;
        int r = idx >> 2, j = idx & 3;
        uint32_t off = r * 64 + j * 16;
        uint32_t sw = SW64R(off);
        const __half* ga = A + (size_t)(m0 + r) * CC + k0 + j * 8;
        cpa16(sbase + 0 * MATB + sw, ga);
        const __half* gb = W2 + (size_t)(n0 + r) * wstride + k0 + j * 8;
        cpa16(sbase + 1 * MATB + sw, gb);
        if (do_wl) cpa16(sbase + 2 * MATB + sw, gb + CC);
    }
}

__global__ __launch_bounds__(256, 2) void gemm_mma(
    const __half* __restrict__ A, const __half* __restrict__ W2,
    const float* __restrict__ bias, float* __restrict__ C, int ldc,
    int wstride, int nskip, __half* __restrict__ vout, int vcol0)
{
    extern __shared__ char sm[];
    const uint32_t sb = smem_u32(sm);
    const int t = threadIdx.x, lane = t & 31, w = t >> 5;
    const int wm = (w >> 2) * 64, wn = (w & 3) * 32;
    const int m0 = blockIdx.y * GBM, n0 = blockIdx.x * GBN;
    const bool do_wl = n0 < nskip;

    const int lrow = lane & 15;
    const int lcol = (lane >> 4) << 3;

    float acc[4][4][4];
#pragma unroll
    for (int i = 0; i < 4; i++)
#pragma unroll
        for (int j = 0; j < 4; j++)
#pragma unroll
            for (int r = 0; r < 4; r++) acc[i][j][r] = 0.f;

#define LDA(fr, mb, kb)                                                             \
    do {                                                                            \
        _Pragma("unroll")                                                           \
        for (int mi = 0; mi < 4; mi++) {                                            \
            uint32_t off = (wm + mi * 16 + lrow) * 64 + ((kb) + lcol) * 2;          \
            ldsm4(fr[mi], (mb) + SW64R(off));                                       \
        }                                                                           \
    } while (0)
#define LDB(fr, mb, kb)                                                             \
    do {                                                                            \
        _Pragma("unroll")                                                           \
        for (int bj = 0; bj < 2; bj++) {                                            \
            uint32_t r4[4];                                                         \
            uint32_t off = (wn + bj * 16 + lrow) * 64 + ((kb) + lcol) * 2;          \
            ldsm4(r4, (mb) + SW64R(off));                                           \
            fr[2 * bj + 0][0] = r4[0]; fr[2 * bj + 0][1] = r4[2];                   \
            fr[2 * bj + 1][0] = r4[1]; fr[2 * bj + 1][1] = r4[3];                   \
        }                                                                           \
    } while (0)
#define MPASS(af, bf)                                                               \
    do {                                                                            \
        _Pragma("unroll")                                                           \
        for (int mi = 0; mi < 4; mi++)                                              \
            _Pragma("unroll")                                                       \
            for (int nj = 0; nj < 4; nj++)                                          \
                mma_f16(acc[mi][nj], af[mi], bf[nj]);                               \
    } while (0)

    g2s_chunk(sb, A, W2, m0, n0, 0, t, wstride, do_wl);
    asm volatile("cp.async.commit_group;" ::: "memory");
    g2s_chunk(sb + STG, A, W2, m0, n0, GBK, t, wstride, do_wl);
    asm volatile("cp.async.commit_group;" ::: "memory");
    g2s_chunk(sb + 2 * STG, A, W2, m0, n0, 2 * GBK, t, wstride, do_wl);
    asm volatile("cp.async.commit_group;" ::: "memory");

    int stage = 0, wstage = 3;
    for (int c = 0; c < NCH; c++) {
        if (c <= NCH - 3)      asm volatile("cp.async.wait_group 2;" ::: "memory");
        else if (c == NCH - 2) asm volatile("cp.async.wait_group 1;" ::: "memory");
        else                   asm volatile("cp.async.wait_group 0;" ::: "memory");
        __syncthreads();
        if (c + 3 < NCH) {
            g2s_chunk(sb + wstage * STG, A, W2, m0, n0, (c + 3) * GBK, t, wstride, do_wl);
            asm volatile("cp.async.commit_group;" ::: "memory");
            wstage = (wstage + 1) & 3;
        }
        const uint32_t st = sb + stage * STG;
        stage = (stage + 1) & 3;

#pragma unroll
        for (int ks = 0; ks < 2; ks++) {
            const int kb = ks * 16;
            uint32_t ah[4][4], bh[4][2];
            LDA(ah, st, kb);
            LDB(bh, st + 1 * MATB, kb);
            MPASS(ah, bh);
            if (do_wl) {
                uint32_t bl[4][2];
                LDB(bl, st + 2 * MATB, kb);
                MPASS(ah, bl);
            }
        }
    }

    // epilogue
    const int group = lane >> 2, tig = lane & 3;
    const bool to_v = (vout != nullptr) && (n0 >= vcol0);
#pragma unroll
    for (int mi = 0; mi < 4; mi++)
#pragma unroll
        for (int nj = 0; nj < 4; nj++) {
            int r0 = m0 + wm + mi * 16 + group;
            int cc0 = n0 + wn + nj * 8 + tig * 2;
            if (to_v) {
                int vc = cc0 - vcol0;
                __half2 h0 = __floats2half2_rn(acc[mi][nj][0], acc[mi][nj][1]);
                __half2 h1 = __floats2half2_rn(acc[mi][nj][2], acc[mi][nj][3]);
                *(__half2*)(vout + (size_t)r0 * CC + vc)       = h0;
                *(__half2*)(vout + (size_t)(r0 + 8) * CC + vc) = h1;
            } else {
                float b0 = 0.f, b1 = 0.f;
                if (bias) { b0 = bias[cc0]; b1 = bias[cc0 + 1]; }
                float2 v0 = make_float2(acc[mi][nj][0] + b0, acc[mi][nj][1] + b1);
                float2 v1 = make_float2(acc[mi][nj][2] + b0, acc[mi][nj][3] + b1);
                *(float2*)(C + (size_t)r0 * ldc + cc0)       = v0;
                *(float2*)(C + (size_t)(r0 + 8) * ldc + cc0) = v1;
            }
        }
}

// ====================== split f32 -> (hi|lo) fp16 (weights) ======================
__global__ __launch_bounds__(256) void split_kernel(
    const float* __restrict__ in, __half* __restrict__ out, int rows)
{
    size_t idx = (size_t)blockIdx.x * 256 + threadIdx.x;
    size_t row = idx >> 8;
    if (row >= (size_t)rows) return;
    int c4 = (int)(idx & 255) << 2;
    float4 v = *(const float4*)(in + row * CC + c4);
    float vv[4] = {v.x, v.y, v.z, v.w};
    __half hb[4], lb[4];
#pragma unroll
    for (int j = 0; j < 4; j++) {
        hb[j] = __float2half_rn(vv[j]);
        lb[j] = __float2half_rn(vv[j] - __half2float(hb[j]));
    }
    *(uint64_t*)(out + row * K2 + c4)      = *(uint64_t*)hb;
    *(uint64_t*)(out + row * K2 + CC + c4) = *(uint64_t*)lb;
}

// ====================== round f32 -> dense fp16 ==================================
__global__ __launch_bounds__(256) void round_kernel(
    const float* __restrict__ in, __half* __restrict__ out, int n4)
{
    int idx = blockIdx.x * 256 + threadIdx.x;
    if (idx >= n4) return;
    float4 v = *(const float4*)(in + (size_t)idx * 4);
    __half hb[4] = {__float2half_rn(v.x), __float2half_rn(v.y),
                    __float2half_rn(v.z), __float2half_rn(v.w)};
    *(uint64_t*)(out + (size_t)idx * 4) = *(uint64_t*)hb;
}

// ================ focus: f32 q,k (ldc 2048) -> fp16 g_qh, g_kh ===================
__global__ __launch_bounds__(256) void focus_kernel(
    const float* __restrict__ scale, const float* __restrict__ pos_enc)
{
    const int row = blockIdx.x;
    const int n = row & (SEQ - 1);
    const float* qp = g_qkv + (size_t)row * 2048;
    const float* kp = qp + CC;
    const int t = threadIdx.x;
    const int c0 = t * 4;

    float4 q4 = *(const float4*)(qp + c0);
    float4 k4 = *(const float4*)(kp + c0);
    const float4 pe  = *(const float4*)(pos_enc + (size_t)n * CC + c0);
    const float4 sc4 = *(const float4*)(scale + c0);

    float qv[4] = {q4.x, q4.y, q4.z, q4.w};
    float kv[4] = {k4.x + pe.x, k4.y + pe.y, k4.z + pe.z, k4.w + pe.w};
    float sv[4] = {sc4.x, sc4.y, sc4.z, sc4.w};

    float s2q = 0.f, s6q = 0.f, s2k = 0.f, s6k = 0.f;
#pragma unroll
    for (int j = 0; j < 4; j++) {
        float sc = log1pf(expf(sv[j]));
        float q = (fmaxf(qv[j], 0.f) + EPS) / sc;
        float k = (fmaxf(kv[j], 0.f) + EPS) / sc;
        qv[j] = q; kv[j] = k;
        float q2 = q * q, k2 = k * k;
        s2q += q2; s2k += k2;
        float q3 = q2 * q, k3 = k2 * k;
        s6q += q3 * q3; s6k += k3 * k3;
    }
    __shared__ float red[8][4];
    const int lid = t & 31, wid = t >> 5;
#pragma unroll
    for (int o = 16; o > 0; o >>= 1) {
        s2q += __shfl_xor_sync(0xffffffffu, s2q, o);
        s6q += __shfl_xor_sync(0xffffffffu, s6q, o);
        s2k += __shfl_xor_sync(0xffffffffu, s2k, o);
        s6k += __shfl_xor_sync(0xffffffffu, s6k, o);
    }
    if (lid == 0) { red[wid][0] = s2q; red[wid][1] = s6q; red[wid][2] = s2k; red[wid][3] = s6k; }
    __syncthreads();
    float t2q = 0.f, t6q = 0.f, t2k = 0.f, t6k = 0.f;
#pragma unroll
    for (int wq = 0; wq < 8; wq++) {
        t2q += red[wq][0]; t6q += red[wq][1]; t2k += red[wq][2]; t6k += red[wq][3];
    }
    const float fq = sqrtf(t2q / t6q);
    const float fk = sqrtf(t2k / t6k);

    __half qo[4], ko[4];
#pragma unroll
    for (int j = 0; j < 4; j++) {
        qo[j] = __float2half_rn(qv[j] * qv[j] * qv[j] * fq);
        ko[j] = __float2half_rn(kv[j] * kv[j] * kv[j] * fk);
    }
    *(uint64_t*)(g_qh + (size_t)row * CC + c0) = *(uint64_t*)qo;
    *(uint64_t*)(g_kh + (size_t)row * CC + c0) = *(uint64_t*)ko;
}

__global__ void zero_kv_kernel()
{
    int i = blockIdx.x * 256 + threadIdx.x;
    if (i < BH * DD * DD) g_kv[i] = 0.f;
    if (i < BH * DD)      g_ksum[i] = 0.f;
}

// ===================== kv = k^T v via HMMA (trans ldmatrix) ======================
// Per (bh, split): chunk of 512 seq. kv[c][d] += sum_n k[n][c] v[n][d].
// A = k^T via trans-ldmatrix of kh tiles; B = v^T via trans-ldmatrix of vh tiles.
// ksum via constant all-ones B fragment.
#define NSPLIT 8
#define NCHUNK (SEQ / NSPLIT)   // 512
#define KVTILE 8192             // 64 rows x 128B

// trans-fragment: 16x16 block at (k0row rows, m0col cols) of [k][m] smem tile
#define TLDSM4(fr, base, k0row, m0col)                                              \
    do {                                                                            \
        uint32_t off = ((k0row) + (lane & 7) + ((lane >> 4) & 1) * 8) * 128         \
                     + ((m0col) + ((lane >> 3) & 1) * 8) * 2;                       \
        ldsm4t(fr, (base) + SW128(off));                                            \
    } while (0)

__global__ __launch_bounds__(128) void kv_kernel()
{
    extern __shared__ char sm[];
    const uint32_t sb = smem_u32(sm);
    const int bh = blockIdx.x, sp = blockIdx.y;
    const int b = bh >> 4, h = bh & 15;
    const int n0 = sp * NCHUNK;
    const int t = threadIdx.x, lane = t & 31, w = t >> 5;
    const int m0w = w * 16;                 // warp's c-range

    // smem: 2 stages x (kh | vh) 8KB each
    float acc[8][4];
#pragma unroll
    for (int i = 0; i < 8; i++)
#pragma unroll
        for (int j = 0; j < 4; j++) acc[i][j] = 0.f;
    float aks[4] = {0.f, 0.f, 0.f, 0.f};
    uint32_t bones[2] = {0x3C003C00u, 0x3C003C00u};

#define KV_LOAD(s0, stg)                                                            \
    do {                                                                            \
        _Pragma("unroll")                                                           \
        for (int i = 0; i < 4; i++) {                                               \
            int idx = t + i * 128;                                                  \
            int r = idx >> 3, j = idx & 7;                                          \
            uint32_t off = SW128((uint32_t)(r * 128 + j * 16));                     \
            size_t grow = ((size_t)(b * SEQ + n0 + (s0) + r)) * CC + h * DD + j * 8;\
            cpa16(sb + (stg) * 2 * KVTILE + off, g_kh + grow);                      \
            cpa16(sb + (stg) * 2 * KVTILE + KVTILE + off, g_vh + grow);             \
        }                                                                           \
    } while (0)

    KV_LOAD(0, 0);
    asm volatile("cp.async.commit_group;" ::: "memory");

    const int NT = NCHUNK / 64;             // 8 tiles
    for (int tl = 0; tl < NT; tl++) {
        if (tl + 1 < NT) {
            KV_LOAD((tl + 1) * 64, (tl + 1) & 1);
            asm volatile("cp.async.commit_group;" ::: "memory");
            asm volatile("cp.async.wait_group 1;" ::: "memory");
        } else {
            asm volatile("cp.async.wait_group 0;" ::: "memory");
        }
        __syncthreads();
        const uint32_t kh_b = sb + (tl & 1) * 2 * KVTILE;
        const uint32_t vh_b = kh_b + KVTILE;
#pragma unroll
        for (int ks = 0; ks < 4; ks++) {
            uint32_t a[4];
            TLDSM4(a, kh_b, ks * 16, m0w);
            uint32_t bfr[8][2];
#pragma unroll
            for (int bj = 0; bj < 4; bj++) {
                uint32_t r4[4];
                TLDSM4(r4, vh_b, ks * 16, bj * 16);
                bfr[2 * bj + 0][0] = r4[0]; bfr[2 * bj + 0][1] = r4[2];
                bfr[2 * bj + 1][0] = r4[1]; bfr[2 * bj + 1][1] = r4[3];
            }
#pragma unroll
            for (int dt = 0; dt < 8; dt++)
                mma_f16(acc[dt], a, bfr[dt]);
            mma_f16(aks, a, bones);
        }
        __syncthreads();
    }

    const int group = lane >> 2, tig = lane & 3;
    const int c0 = m0w + group;
#pragma unroll
    for (int dt = 0; dt < 8; dt++) {
        int d0 = dt * 8 + tig * 2;
        atomicAdd(&g_kv[(size_t)bh * 4096 + c0 * 64 + d0],           acc[dt][0]);
        atomicAdd(&g_kv[(size_t)bh * 4096 + c0 * 64 + d0 + 1],       acc[dt][1]);
        atomicAdd(&g_kv[(size_t)bh * 4096 + (c0 + 8) * 64 + d0],     acc[dt][2]);
        atomicAdd(&g_kv[(size_t)bh * 4096 + (c0 + 8) * 64 + d0 + 1], acc[dt][3]);
    }
    if (tig == 0) {
        atomicAdd(&g_ksum[bh * 64 + c0],     aks[0]);
        atomicAdd(&g_ksum[bh * 64 + c0 + 8], aks[2]);
    }
}

// ====================== kv f32 [c][d] -> kv^T fp16 [d][c] ========================
__global__ __launch_bounds__(64) void kvcvt_kernel()
{
    const int bh = blockIdx.x, d = threadIdx.x;
    __half row[64];
#pragma unroll 16
    for (int c = 0; c < 64; c++)
        row[c] = __float2half_rn(g_kv[(size_t)bh * 4096 + c * 64 + d]);
#pragma unroll
    for (int j = 0; j < 16; j++)
        *(uint64_t*)(g_kvt + (size_t)bh * 4096 + d * 64 + j * 4) = *(uint64_t*)(row + j * 4);
}

// =========== o = z * (q @ kv) via HMMA; q fp16, kv^T fp16; out fp16 ==============
__global__ __launch_bounds__(128) void o_kernel()
{
    extern __shared__ char sm[];
    const uint32_t sb = smem_u32(sm);
    const int bh = blockIdx.x, ic = blockIdx.y;
    const int b = bh >> 4, h = bh & 15;
    const int i0 = ic * 64;
    const int t = threadIdx.x, lane = t & 31, w = t >> 5;
    const int m0w = w * 16;
    const int lrow = lane & 15, lcol = (lane >> 4) << 3;

    // smem: qs 8KB | kvt 8KB | ksum 256B | z 256B
    const uint32_t qs = sb, kvs = sb + KVTILE;
    float* ksum_s = (float*)(sm + 2 * KVTILE);
    float* z_s    = (float*)(sm + 2 * KVTILE + 256);

#pragma unroll
    for (int i = 0; i < 4; i++) {
        int idx = t + i * 128;
        int r = idx >> 3, j = idx & 7;
        uint32_t off = SW128((uint32_t)(r * 128 + j * 16));
        cpa16(qs + off, g_qh + ((size_t)(b * SEQ + i0 + r)) * CC + h * DD + j * 8);
        cpa16(kvs + off, g_kvt + (size_t)bh * 4096 + r * 64 + j * 8);
    }
    asm volatile("cp.async.commit_group;" ::: "memory");
    if (t < 64) ksum_s[t] = g_ksum[bh * 64 + t];
    asm volatile("cp.async.wait_group 0;" ::: "memory");
    __syncthreads();

    // z per row: thread pair (t, t^1) covers row t>>1
    {
        int r = t >> 1, half = t & 1;
        float s = 0.f;
#pragma unroll 8
        for (int cc = half * 32; cc < half * 32 + 32; cc++) {
            uint32_t off = SW128((uint32_t)(r * 128 + cc * 2));
            __half qv = *(__half*)(sm + off);
            s += __half2float(qv) * ksum_s[cc];
        }
        s += __shfl_xor_sync(0xffffffffu, s, 1);
        if (half == 0) z_s[r] = 1.0f / (s + EPS);
    }
    __syncthreads();

    float acc[8][4];
#pragma unroll
    for (int i = 0; i < 8; i++)
#pragma unroll
        for (int j = 0; j < 4; j++) acc[i][j] = 0.f;

#pragma unroll
    for (int ks = 0; ks < 4; ks++) {
        const int kb = ks * 16;
        uint32_t a[4];
        {
            uint32_t off = (m0w + lrow) * 128 + (kb + lcol) * 2;
            ldsm4(a, qs + SW128(off));
        }
        uint32_t bfr[8][2];
#pragma unroll
        for (int bj = 0; bj < 2; bj++) {
            uint32_t r4[4];
            uint32_t off = (bj * 32 + lrow) * 128 + (kb + lcol) * 2;
            ldsm4(r4, kvs + SW128(off));
            bfr[4 * bj + 0][0] = r4[0]; bfr[4 * bj + 0][1] = r4[2];
            bfr[4 * bj + 1][0] = r4[1]; bfr[4 * bj + 1][1] = r4[3];
            off = (bj * 32 + 16 + lrow) * 128 + (kb + lcol) * 2;
            ldsm4(r4, kvs + SW128(off));
            bfr[4 * bj + 2][0] = r4[0]; bfr[4 * bj + 2][1] = r4[2];
            bfr[4 * bj + 3][0] = r4[1]; bfr[4 * bj + 3][1] = r4[3];
        }
#pragma unroll
        for (int dt = 0; dt < 8; dt++)
            mma_f16(acc[dt], a, bfr[dt]);
    }

    const int group = lane >> 2, tig = lane & 3;
    const float z0 = z_s[m0w + group], z1 = z_s[m0w + group + 8];
    const size_t r0 = (size_t)(b * SEQ + i0 + m0w + group);
#pragma unroll
    for (int dt = 0; dt < 8; dt++) {
        int d0 = h * DD + dt * 8 + tig * 2;
        __half2 h0 = __floats2half2_rn(acc[dt][0] * z0, acc[dt][1] * z0);
        __half2 h1 = __floats2half2_rn(acc[dt][2] * z1, acc[dt][3] * z1);
        *(__half2*)(g_oh + r0 * CC + d0)       = h0;
        *(__half2*)(g_oh + (r0 + 8) * CC + d0) = h1;
    }
}

// =================================================================================
extern "C" void kernel_launch(void* const* d_in, const int* in_sizes, int n_in,
                              void* d_out, int out_size)
{
    const float* x       = (const float*)d_in[0];
    const float* scale   = (const float*)d_in[1];
    const float* pos_enc = (const float*)d_in[2];
    const float* qkv_w   = (const float*)d_in[3];
    const float* proj_w  = (const float*)d_in[4];
    const float* proj_b  = (const float*)d_in[5];
    float* out = (float*)d_out;

    float *qkv_p = nullptr;
    __half *xh_p = nullptr, *oh_p = nullptr, *wq2_p = nullptr, *wph_p = nullptr, *vh_p = nullptr;
    cudaGetSymbolAddress((void**)&qkv_p, g_qkv);
    cudaGetSymbolAddress((void**)&xh_p, g_xh);
    cudaGetSymbolAddress((void**)&oh_p, g_oh);
    cudaGetSymbolAddress((void**)&wq2_p, g_wq2);
    cudaGetSymbolAddress((void**)&wph_p, g_wph);
    cudaGetSymbolAddress((void**)&vh_p, g_vh);

    cudaFuncSetAttribute(gemm_mma, cudaFuncAttributeMaxDynamicSharedMemorySize, GSMEM);

    // 0) fp16 prep
    round_kernel<<<(MM * CC / 4 + 255) / 256, 256>>>(x, xh_p, MM * CC / 4);
    split_kernel<<<C3, 256>>>(qkv_w, wq2_p, C3);
    round_kernel<<<(CC * CC / 4 + 255) / 256, 256>>>(proj_w, wph_p, CC * CC / 4);
    // 1) qkv: q,k f32 (2-pass, ldc 2048); v fp16 (1-pass) straight to g_vh
    gemm_mma<<<dim3(C3 / GBN, MM / GBM), 256, GSMEM>>>(
        xh_p, wq2_p, nullptr, qkv_p, 2048, K2, 2048, vh_p, 2048);
    // 2) focus -> fp16 q,k
    focus_kernel<<<MM, 256>>>(scale, pos_enc);
    // 3) kv = k^T v (+ ksum) via HMMA
    zero_kv_kernel<<<(BH * DD * DD + 255) / 256, 256>>>();
    kv_kernel<<<dim3(BH, NSPLIT), 128, 2 * 2 * KVTILE>>>();
    kvcvt_kernel<<<BH, 64>>>();
    // 4) o = z * (q @ kv) via HMMA -> fp16
    o_kernel<<<dim3(BH, SEQ / 64), 128, 2 * KVTILE + 512>>>();
    // 5) out = o @ proj_w^T + proj_b (single-pass fp16)
    gemm_mma<<<dim3(CC / GBN, MM / GBM), 256, GSMEM>>>(
        oh_p, wph_p, proj_b, out, CC, CC, 0, nullptr, 0);
}